// round 1
// baseline (speedup 1.0000x reference)
#include <cuda_runtime.h>
#include <math.h>

#define N_NODES 50000
#define N_EDGES 600000
#define IN_DIM 256
#define HID 128
#define OUT_DIM 10
#define BN_EPS 1e-5f

// ---------------- scratch (static __device__ — no allocations) ----------------
__device__ float g_h[N_NODES * HID];      // activations
__device__ float g_hw[N_NODES * HID];     // h @ Wc
__device__ float g_t[N_NODES * HID];      // conv output (pre-BN)
__device__ int   g_deg[N_NODES];
__device__ int   g_rowptr[N_NODES + 1];
__device__ int   g_cursor[N_NODES];
__device__ float g_dinv[N_NODES];
__device__ int   g_csr_src[N_EDGES];
__device__ float g_csr_w[N_EDGES];        // dinv[src] per edge
__device__ float g_sum[HID];
__device__ float g_sumsq[HID];
__device__ int   g_is64;

// ---------------- edge dtype detection (jax int64 vs silent int32) ------------
__global__ void detect_kernel(const void* ei) {
    __shared__ int bad;
    if (threadIdx.x == 0) bad = 0;
    __syncthreads();
    const long long* p = (const long long*)ei;
    for (int i = threadIdx.x; i < 4096; i += blockDim.x) {
        long long v = p[i];
        if (v < 0 || v >= N_NODES) atomicExch(&bad, 1);
    }
    __syncthreads();
    if (threadIdx.x == 0) g_is64 = bad ? 0 : 1;
}

__device__ __forceinline__ void load_edge(const void* ei, int e, int& s, int& d) {
    if (g_is64) {
        const long long* p = (const long long*)ei;
        s = (int)p[e];
        d = (int)p[N_EDGES + e];
    } else {
        const int* p = (const int*)ei;
        s = p[e];
        d = p[N_EDGES + e];
    }
}

// ---------------- CSR build ----------------
__global__ void zero_deg_kernel() {
    for (int i = blockIdx.x * blockDim.x + threadIdx.x; i < N_NODES;
         i += gridDim.x * blockDim.x)
        g_deg[i] = 0;
}

__global__ void count_deg_kernel(const void* ei) {
    for (int e = blockIdx.x * blockDim.x + threadIdx.x; e < N_EDGES;
         e += gridDim.x * blockDim.x) {
        int s, d;
        load_edge(ei, e, s, d);
        atomicAdd(&g_deg[d], 1);
    }
}

// single-block scan over 50000 degrees -> rowptr, cursor, dinv
__global__ void scan_kernel() {
    __shared__ int wsum[32];
    __shared__ int s_carry;
    int tid = threadIdx.x, lane = tid & 31, wid = tid >> 5;
    if (tid == 0) s_carry = 0;
    __syncthreads();
    for (int base = 0; base < N_NODES; base += 1024) {
        int i = base + tid;
        int d = (i < N_NODES) ? g_deg[i] : 0;
        int incl = d;
        #pragma unroll
        for (int off = 1; off < 32; off <<= 1) {
            int v = __shfl_up_sync(0xffffffffu, incl, off);
            if (lane >= off) incl += v;
        }
        if (lane == 31) wsum[wid] = incl;
        __syncthreads();
        if (wid == 0) {
            int v = wsum[lane];
            int wi = v;
            #pragma unroll
            for (int off = 1; off < 32; off <<= 1) {
                int t2 = __shfl_up_sync(0xffffffffu, wi, off);
                if (lane >= off) wi += t2;
            }
            wsum[lane] = wi - v;  // exclusive warp offsets
        }
        __syncthreads();
        int carry = s_carry;
        int excl = carry + wsum[wid] + incl - d;
        if (i < N_NODES) {
            g_rowptr[i] = excl;
            g_cursor[i] = excl;
            g_dinv[i]   = rsqrtf((float)d + 1.0f);
        }
        __syncthreads();
        if (tid == 1023) s_carry = carry + wsum[31] + incl;
        __syncthreads();
    }
    if (threadIdx.x == 0) g_rowptr[N_NODES] = s_carry;
}

__global__ void build_csr_kernel(const void* ei) {
    for (int e = blockIdx.x * blockDim.x + threadIdx.x; e < N_EDGES;
         e += gridDim.x * blockDim.x) {
        int s, d;
        load_edge(ei, e, s, d);
        int pos = atomicAdd(&g_cursor[d], 1);
        g_csr_src[pos] = s;
        g_csr_w[pos]   = g_dinv[s];
    }
}

// ---------------- SGEMM: C[N x 128] = A[N x K] @ W[K x 128] (+bias, relu) -----
__global__ __launch_bounds__(256)
void gemm_kernel(const float* __restrict__ A, const float* __restrict__ W,
                 const float* __restrict__ bias, float* __restrict__ C,
                 int N, int K, int do_relu) {
    __shared__ float As[32][132];  // [k][row], padded
    __shared__ float Ws[32][128];  // [k][col]
    int tid = threadIdx.x;
    int tx = tid & 15, ty = tid >> 4;
    int row0 = blockIdx.x * 128;
    float acc[8][8] = {};

    for (int k0 = 0; k0 < K; k0 += 32) {
        #pragma unroll
        for (int p = 0; p < 4; p++) {
            int r  = p * 32 + (tid >> 3);
            int kk = (tid & 7) * 4;
            int grow = row0 + r;
            float4 v = make_float4(0.f, 0.f, 0.f, 0.f);
            if (grow < N) v = *(const float4*)&A[(size_t)grow * K + k0 + kk];
            As[kk + 0][r] = v.x; As[kk + 1][r] = v.y;
            As[kk + 2][r] = v.z; As[kk + 3][r] = v.w;
        }
        #pragma unroll
        for (int p = 0; p < 4; p++) {
            int kk = p * 8 + (tid >> 5);
            int c  = (tid & 31) * 4;
            *(float4*)&Ws[kk][c] = *(const float4*)&W[(size_t)(k0 + kk) * HID + c];
        }
        __syncthreads();
        #pragma unroll
        for (int kk = 0; kk < 32; kk++) {
            float a[8], b[8];
            #pragma unroll
            for (int i = 0; i < 8; i++) a[i] = As[kk][ty * 8 + i];
            #pragma unroll
            for (int j = 0; j < 8; j++) b[j] = Ws[kk][tx * 8 + j];
            #pragma unroll
            for (int i = 0; i < 8; i++)
                #pragma unroll
                for (int j = 0; j < 8; j++)
                    acc[i][j] += a[i] * b[j];
        }
        __syncthreads();
    }

    int c0 = tx * 8;
    float bb[8];
    #pragma unroll
    for (int j = 0; j < 8; j++) bb[j] = bias ? bias[c0 + j] : 0.f;
    #pragma unroll
    for (int i = 0; i < 8; i++) {
        int grow = row0 + ty * 8 + i;
        if (grow < N) {
            float4 v0, v1;
            float r_[8];
            #pragma unroll
            for (int j = 0; j < 8; j++) {
                float v = acc[i][j] + bb[j];
                if (do_relu) v = fmaxf(v, 0.f);
                r_[j] = v;
            }
            v0 = make_float4(r_[0], r_[1], r_[2], r_[3]);
            v1 = make_float4(r_[4], r_[5], r_[6], r_[7]);
            *(float4*)&C[(size_t)grow * HID + c0]     = v0;
            *(float4*)&C[(size_t)grow * HID + c0 + 4] = v1;
        }
    }
}

// ---------------- per-layer: zero BN stats ----------------
__global__ void zero_stats_kernel() {
    int i = threadIdx.x;
    if (i < HID) { g_sum[i] = 0.f; g_sumsq[i] = 0.f; }
}

// ---------------- aggregation (gather CSR) + self-loop + bias + BN stats ------
__global__ __launch_bounds__(256)
void agg_kernel(const float* __restrict__ hw, const float* __restrict__ bc,
                float* __restrict__ t) {
    __shared__ float s_sum[HID], s_sq[HID];
    int tid = threadIdx.x;
    if (tid < HID) { s_sum[tid] = 0.f; s_sq[tid] = 0.f; }
    __syncthreads();

    int lane = tid & 31;
    int n = blockIdx.x * 8 + (tid >> 5);
    if (n < N_NODES) {
        int e0 = g_rowptr[n], e1 = g_rowptr[n + 1];
        float a0 = 0.f, a1 = 0.f, a2 = 0.f, a3 = 0.f;
        int e = e0;
        int s_next = 0; float w_next = 0.f;
        if (e < e1) { s_next = __ldg(&g_csr_src[e]); w_next = __ldg(&g_csr_w[e]); }
        while (e < e1) {
            int s = s_next; float w = w_next;
            e++;
            if (e < e1) { s_next = __ldg(&g_csr_src[e]); w_next = __ldg(&g_csr_w[e]); }
            float4 v = *(const float4*)(hw + s * HID + lane * 4);
            a0 += v.x * w; a1 += v.y * w; a2 += v.z * w; a3 += v.w * w;
        }
        float di  = g_dinv[n];
        float dii = di * di;
        int c = lane * 4;
        float4 sv = *(const float4*)(hw + n * HID + c);
        float t0 = a0 * di + sv.x * dii + bc[c + 0];
        float t1 = a1 * di + sv.y * dii + bc[c + 1];
        float t2 = a2 * di + sv.z * dii + bc[c + 2];
        float t3 = a3 * di + sv.w * dii + bc[c + 3];
        *(float4*)(t + n * HID + c) = make_float4(t0, t1, t2, t3);
        atomicAdd(&s_sum[c + 0], t0); atomicAdd(&s_sq[c + 0], t0 * t0);
        atomicAdd(&s_sum[c + 1], t1); atomicAdd(&s_sq[c + 1], t1 * t1);
        atomicAdd(&s_sum[c + 2], t2); atomicAdd(&s_sq[c + 2], t2 * t2);
        atomicAdd(&s_sum[c + 3], t3); atomicAdd(&s_sq[c + 3], t3 * t3);
    }
    __syncthreads();
    if (tid < HID) {
        atomicAdd(&g_sum[tid],   s_sum[tid]);
        atomicAdd(&g_sumsq[tid], s_sq[tid]);
    }
}

// ---------------- BN apply + relu + residual ----------------
__global__ __launch_bounds__(256)
void bn_apply_kernel(const float* __restrict__ t, float* __restrict__ h,
                     const float* __restrict__ gamma, const float* __restrict__ beta,
                     int add_res) {
    __shared__ float s_scale[HID], s_shift[HID];
    int tid = threadIdx.x;
    if (tid < HID) {
        float mu  = g_sum[tid] * (1.0f / N_NODES);
        float var = g_sumsq[tid] * (1.0f / N_NODES) - mu * mu;
        float sc  = gamma[tid] * rsqrtf(var + BN_EPS);
        s_scale[tid] = sc;
        s_shift[tid] = beta[tid] - mu * sc;
    }
    __syncthreads();
    int total4 = N_NODES * HID / 4;
    for (int i = blockIdx.x * blockDim.x + tid; i < total4;
         i += gridDim.x * blockDim.x) {
        int c = (i * 4) & (HID - 1);
        float4 v = ((const float4*)t)[i];
        v.x = fmaxf(v.x * s_scale[c + 0] + s_shift[c + 0], 0.f);
        v.y = fmaxf(v.y * s_scale[c + 1] + s_shift[c + 1], 0.f);
        v.z = fmaxf(v.z * s_scale[c + 2] + s_shift[c + 2], 0.f);
        v.w = fmaxf(v.w * s_scale[c + 3] + s_shift[c + 3], 0.f);
        if (add_res) {
            float4 r = ((const float4*)h)[i];
            v.x += r.x; v.y += r.y; v.z += r.z; v.w += r.w;
        }
        ((float4*)h)[i] = v;
    }
}

// ---------------- output projection: [N,128] @ [128,10] + b ------------------
__global__ __launch_bounds__(256)
void out_kernel(const float* __restrict__ h, const float* __restrict__ Wo,
                const float* __restrict__ bo, float* __restrict__ out) {
    __shared__ float ws[HID * OUT_DIM];
    __shared__ float bs[OUT_DIM];
    for (int i = threadIdx.x; i < HID * OUT_DIM; i += blockDim.x) ws[i] = Wo[i];
    if (threadIdx.x < OUT_DIM) bs[threadIdx.x] = bo[threadIdx.x];
    __syncthreads();
    int n = blockIdx.x * blockDim.x + threadIdx.x;
    if (n >= N_NODES) return;
    float acc[OUT_DIM];
    #pragma unroll
    for (int o = 0; o < OUT_DIM; o++) acc[o] = bs[o];
    const float4* hp = (const float4*)(h + n * HID);
    #pragma unroll 4
    for (int k4 = 0; k4 < HID / 4; k4++) {
        float4 v = hp[k4];
        int kb = k4 * 4;
        #pragma unroll
        for (int o = 0; o < OUT_DIM; o++) {
            acc[o] += v.x * ws[(kb + 0) * OUT_DIM + o]
                    + v.y * ws[(kb + 1) * OUT_DIM + o]
                    + v.z * ws[(kb + 2) * OUT_DIM + o]
                    + v.w * ws[(kb + 3) * OUT_DIM + o];
        }
    }
    #pragma unroll
    for (int o = 0; o < OUT_DIM; o++) out[n * OUT_DIM + o] = acc[o];
}

// ---------------- launch ----------------
extern "C" void kernel_launch(void* const* d_in, const int* in_sizes, int n_in,
                              void* d_out, int out_size) {
    const float* x     = (const float*)d_in[0];
    const void*  ei    = d_in[1];
    const float* W_in  = (const float*)d_in[2];
    const float* b_in  = (const float*)d_in[3];
    const float* Wc    = (const float*)d_in[4];
    const float* bc    = (const float*)d_in[5];
    const float* gamma = (const float*)d_in[6];
    const float* beta  = (const float*)d_in[7];
    const float* W_out = (const float*)d_in[8];
    const float* b_out = (const float*)d_in[9];
    float* out = (float*)d_out;

    float *p_h, *p_hw, *p_t;
    cudaGetSymbolAddress((void**)&p_h,  g_h);
    cudaGetSymbolAddress((void**)&p_hw, g_hw);
    cudaGetSymbolAddress((void**)&p_t,  g_t);

    detect_kernel<<<1, 256>>>(ei);
    zero_deg_kernel<<<98, 512>>>();
    count_deg_kernel<<<586, 1024>>>(ei);
    scan_kernel<<<1, 1024>>>();
    build_csr_kernel<<<586, 1024>>>(ei);

    // input layer: h = relu(x @ W_in + b_in)
    gemm_kernel<<<(N_NODES + 127) / 128, 256>>>(x, W_in, b_in, p_h, N_NODES, IN_DIM, 1);

    for (int i = 0; i < 3; i++) {
        gemm_kernel<<<(N_NODES + 127) / 128, 256>>>(p_h, Wc + i * HID * HID, nullptr,
                                                    p_hw, N_NODES, HID, 0);
        zero_stats_kernel<<<1, 128>>>();
        agg_kernel<<<N_NODES / 8, 256>>>(p_hw, bc + i * HID, p_t);
        bn_apply_kernel<<<1024, 256>>>(p_t, p_h, gamma + i * HID, beta + i * HID, i > 0);
    }

    out_kernel<<<(N_NODES + 255) / 256, 256>>>(p_h, W_out, b_out, out);
}

// round 2
// speedup vs baseline: 1.1203x; 1.1203x over previous
#include <cuda_runtime.h>
#include <math.h>

#define N_NODES 50000
#define N_EDGES 600000
#define IN_DIM 256
#define HID 128
#define OUT_DIM 10
#define BN_EPS 1e-5f

// ---------------- scratch (static __device__ — no allocations) ----------------
__device__ float g_h[N_NODES * HID];      // activations
__device__ float g_hw[N_NODES * HID];     // h @ Wc
__device__ float g_t[N_NODES * HID];      // conv output (pre-BN)
__device__ int   g_deg[N_NODES];
__device__ int   g_rowptr[N_NODES + 1];
__device__ int   g_cursor[N_NODES];
__device__ float g_dinv[N_NODES];
__device__ int   g_csr_src[N_EDGES];
__device__ float g_csr_w[N_EDGES];        // dinv[src] per edge
__device__ float g_sum[HID];
__device__ float g_sumsq[HID];
__device__ int   g_is64;

// ---------------- edge dtype detection (jax int64 vs silent int32) ------------
__global__ void detect_kernel(const void* ei) {
    __shared__ int bad;
    if (threadIdx.x == 0) bad = 0;
    __syncthreads();
    const long long* p = (const long long*)ei;
    for (int i = threadIdx.x; i < 4096; i += blockDim.x) {
        long long v = p[i];
        if (v < 0 || v >= N_NODES) atomicExch(&bad, 1);
    }
    __syncthreads();
    if (threadIdx.x == 0) g_is64 = bad ? 0 : 1;
}

__device__ __forceinline__ void load_edge(const void* ei, int e, int& s, int& d) {
    if (g_is64) {
        const long long* p = (const long long*)ei;
        s = (int)p[e];
        d = (int)p[N_EDGES + e];
    } else {
        const int* p = (const int*)ei;
        s = p[e];
        d = p[N_EDGES + e];
    }
}

// ---------------- CSR build ----------------
__global__ void zero_deg_kernel() {
    for (int i = blockIdx.x * blockDim.x + threadIdx.x; i < N_NODES;
         i += gridDim.x * blockDim.x)
        g_deg[i] = 0;
}

__global__ void count_deg_kernel(const void* ei) {
    for (int e = blockIdx.x * blockDim.x + threadIdx.x; e < N_EDGES;
         e += gridDim.x * blockDim.x) {
        int s, d;
        load_edge(ei, e, s, d);
        atomicAdd(&g_deg[d], 1);
    }
}

// single-block scan, chunk-per-thread: each thread owns a contiguous chunk.
#define SCAN_THREADS 1024
#define SCAN_CHUNK   ((N_NODES + SCAN_THREADS - 1) / SCAN_THREADS)  // 49
__global__ __launch_bounds__(SCAN_THREADS)
void scan_kernel() {
    __shared__ int wsum[32];
    int tid = threadIdx.x, lane = tid & 31, wid = tid >> 5;
    int base = tid * SCAN_CHUNK;
    int end  = min(base + SCAN_CHUNK, N_NODES);

    // 1) serial chunk sum
    int csum = 0;
    for (int i = base; i < end; i++) csum += g_deg[i];

    // 2) block-wide exclusive scan of the 1024 chunk sums
    int incl = csum;
    #pragma unroll
    for (int off = 1; off < 32; off <<= 1) {
        int v = __shfl_up_sync(0xffffffffu, incl, off);
        if (lane >= off) incl += v;
    }
    if (lane == 31) wsum[wid] = incl;
    __syncthreads();
    if (wid == 0) {
        int v = wsum[lane];
        int wi = v;
        #pragma unroll
        for (int off = 1; off < 32; off <<= 1) {
            int t2 = __shfl_up_sync(0xffffffffu, wi, off);
            if (lane >= off) wi += t2;
        }
        wsum[lane] = wi - v;  // exclusive warp offsets
    }
    __syncthreads();
    int excl = wsum[wid] + incl - csum;  // exclusive prefix of this chunk

    // 3) serial write of per-node exclusive offsets (+cursor, dinv)
    int run = excl;
    for (int i = base; i < end; i++) {
        int d = g_deg[i];
        g_rowptr[i] = run;
        g_cursor[i] = run;
        g_dinv[i]   = rsqrtf((float)d + 1.0f);
        run += d;
    }
    if (tid == SCAN_THREADS - 1) g_rowptr[N_NODES] = run;
}

__global__ void build_csr_kernel(const void* ei) {
    for (int e = blockIdx.x * blockDim.x + threadIdx.x; e < N_EDGES;
         e += gridDim.x * blockDim.x) {
        int s, d;
        load_edge(ei, e, s, d);
        int pos = atomicAdd(&g_cursor[d], 1);
        g_csr_src[pos] = s;
        g_csr_w[pos]   = g_dinv[s];
    }
}

// ---------------- tf32 tensor-core GEMM ----------------
// C[N x 128] = A[N x K] @ W[K x 128] (+bias, relu)
// block: 256 thr = 8 warps; block tile 128(M) x 128(N); warp tile 64(M) x 32(N)
// mma.sync.aligned.m16n8k8.row.col.f32.tf32.tf32.f32

__device__ __forceinline__ unsigned f2tf32(float f) {
    unsigned r;
    asm("cvt.rna.tf32.f32 %0, %1;" : "=r"(r) : "f"(f));
    return r;
}

#define APAD 36   // As row stride: banks = m*4 + k -> conflict-free
#define BPAD 136  // Bs row stride: banks = k*8 + n -> conflict-free

__global__ __launch_bounds__(256)
void gemm_tf32_kernel(const float* __restrict__ A, const float* __restrict__ W,
                      const float* __restrict__ bias, float* __restrict__ C,
                      int N, int K, int do_relu) {
    __shared__ unsigned As[128 * APAD];  // [m][k] tf32 bits
    __shared__ unsigned Bs[32 * BPAD];   // [k][n] tf32 bits

    int tid = threadIdx.x;
    int w = tid >> 5, lane = tid & 31;
    int wm = (w & 1) * 64;      // warp M origin within block tile
    int wn = (w >> 1) * 32;     // warp N origin
    int gid = lane >> 2, tig = lane & 3;
    int row0 = blockIdx.x * 128;

    float acc[4][4][4];  // [matom][natom][c0..c3]
    #pragma unroll
    for (int i = 0; i < 4; i++)
        #pragma unroll
        for (int j = 0; j < 4; j++)
            #pragma unroll
            for (int c = 0; c < 4; c++) acc[i][j][c] = 0.f;

    for (int k0 = 0; k0 < K; k0 += 32) {
        // stage A tile: 128 x 32
        #pragma unroll
        for (int p = 0; p < 4; p++) {
            int r  = p * 32 + (tid >> 3);
            int kk = (tid & 7) * 4;
            int grow = row0 + r;
            float4 v = make_float4(0.f, 0.f, 0.f, 0.f);
            if (grow < N) v = *(const float4*)&A[(size_t)grow * K + k0 + kk];
            unsigned* dst = &As[r * APAD + kk];
            dst[0] = f2tf32(v.x); dst[1] = f2tf32(v.y);
            dst[2] = f2tf32(v.z); dst[3] = f2tf32(v.w);
        }
        // stage W tile: 32 x 128
        #pragma unroll
        for (int p = 0; p < 4; p++) {
            int kk = p * 8 + (tid >> 5);
            int c  = (tid & 31) * 4;
            float4 v = *(const float4*)&W[(size_t)(k0 + kk) * HID + c];
            unsigned* dst = &Bs[kk * BPAD + c];
            dst[0] = f2tf32(v.x); dst[1] = f2tf32(v.y);
            dst[2] = f2tf32(v.z); dst[3] = f2tf32(v.w);
        }
        __syncthreads();

        #pragma unroll
        for (int ks = 0; ks < 4; ks++) {
            int k = ks * 8;
            unsigned afr[4][4], bfr[4][2];
            #pragma unroll
            for (int i = 0; i < 4; i++) {
                int m = wm + i * 16;
                afr[i][0] = As[(m + gid)     * APAD + k + tig];
                afr[i][1] = As[(m + gid + 8) * APAD + k + tig];
                afr[i][2] = As[(m + gid)     * APAD + k + tig + 4];
                afr[i][3] = As[(m + gid + 8) * APAD + k + tig + 4];
            }
            #pragma unroll
            for (int j = 0; j < 4; j++) {
                int n = wn + j * 8 + gid;
                bfr[j][0] = Bs[(k + tig)     * BPAD + n];
                bfr[j][1] = Bs[(k + tig + 4) * BPAD + n];
            }
            #pragma unroll
            for (int i = 0; i < 4; i++)
                #pragma unroll
                for (int j = 0; j < 4; j++) {
                    asm volatile(
                        "mma.sync.aligned.m16n8k8.row.col.f32.tf32.tf32.f32 "
                        "{%0,%1,%2,%3}, {%4,%5,%6,%7}, {%8,%9}, {%0,%1,%2,%3};"
                        : "+f"(acc[i][j][0]), "+f"(acc[i][j][1]),
                          "+f"(acc[i][j][2]), "+f"(acc[i][j][3])
                        : "r"(afr[i][0]), "r"(afr[i][1]),
                          "r"(afr[i][2]), "r"(afr[i][3]),
                          "r"(bfr[j][0]), "r"(bfr[j][1]));
                }
        }
        __syncthreads();
    }

    // epilogue: c0/c1 at (m+gid, n+2*tig(+1)), c2/c3 at (m+gid+8, ...)
    #pragma unroll
    for (int i = 0; i < 4; i++) {
        int r_up = row0 + wm + i * 16 + gid;
        int r_dn = r_up + 8;
        #pragma unroll
        for (int j = 0; j < 4; j++) {
            int col = wn + j * 8 + 2 * tig;
            float b0 = bias ? bias[col]     : 0.f;
            float b1 = bias ? bias[col + 1] : 0.f;
            float u0 = acc[i][j][0] + b0, u1 = acc[i][j][1] + b1;
            float d0 = acc[i][j][2] + b0, d1 = acc[i][j][3] + b1;
            if (do_relu) {
                u0 = fmaxf(u0, 0.f); u1 = fmaxf(u1, 0.f);
                d0 = fmaxf(d0, 0.f); d1 = fmaxf(d1, 0.f);
            }
            if (r_up < N) *(float2*)&C[(size_t)r_up * HID + col] = make_float2(u0, u1);
            if (r_dn < N) *(float2*)&C[(size_t)r_dn * HID + col] = make_float2(d0, d1);
        }
    }
}

// ---------------- per-layer: zero BN stats ----------------
__global__ void zero_stats_kernel() {
    int i = threadIdx.x;
    if (i < HID) { g_sum[i] = 0.f; g_sumsq[i] = 0.f; }
}

// ---------------- aggregation (gather CSR) + self-loop + bias + BN stats ------
__global__ __launch_bounds__(256)
void agg_kernel(const float* __restrict__ hw, const float* __restrict__ bc,
                float* __restrict__ t) {
    __shared__ float s_sum[HID], s_sq[HID];
    int tid = threadIdx.x;
    if (tid < HID) { s_sum[tid] = 0.f; s_sq[tid] = 0.f; }
    __syncthreads();

    int lane = tid & 31;
    int n = blockIdx.x * 8 + (tid >> 5);
    if (n < N_NODES) {
        int e0 = g_rowptr[n], e1 = g_rowptr[n + 1];
        float a0 = 0.f, a1 = 0.f, a2 = 0.f, a3 = 0.f;
        int e = e0;
        int s_next = 0; float w_next = 0.f;
        if (e < e1) { s_next = __ldg(&g_csr_src[e]); w_next = __ldg(&g_csr_w[e]); }
        while (e < e1) {
            int s = s_next; float w = w_next;
            e++;
            if (e < e1) { s_next = __ldg(&g_csr_src[e]); w_next = __ldg(&g_csr_w[e]); }
            float4 v = *(const float4*)(hw + s * HID + lane * 4);
            a0 += v.x * w; a1 += v.y * w; a2 += v.z * w; a3 += v.w * w;
        }
        float di  = g_dinv[n];
        float dii = di * di;
        int c = lane * 4;
        float4 sv = *(const float4*)(hw + n * HID + c);
        float t0 = a0 * di + sv.x * dii + bc[c + 0];
        float t1 = a1 * di + sv.y * dii + bc[c + 1];
        float t2 = a2 * di + sv.z * dii + bc[c + 2];
        float t3 = a3 * di + sv.w * dii + bc[c + 3];
        *(float4*)(t + n * HID + c) = make_float4(t0, t1, t2, t3);
        atomicAdd(&s_sum[c + 0], t0); atomicAdd(&s_sq[c + 0], t0 * t0);
        atomicAdd(&s_sum[c + 1], t1); atomicAdd(&s_sq[c + 1], t1 * t1);
        atomicAdd(&s_sum[c + 2], t2); atomicAdd(&s_sq[c + 2], t2 * t2);
        atomicAdd(&s_sum[c + 3], t3); atomicAdd(&s_sq[c + 3], t3 * t3);
    }
    __syncthreads();
    if (tid < HID) {
        atomicAdd(&g_sum[tid],   s_sum[tid]);
        atomicAdd(&g_sumsq[tid], s_sq[tid]);
    }
}

// ---------------- BN apply + relu + residual ----------------
__global__ __launch_bounds__(256)
void bn_apply_kernel(const float* __restrict__ t, float* __restrict__ h,
                     const float* __restrict__ gamma, const float* __restrict__ beta,
                     int add_res) {
    __shared__ float s_scale[HID], s_shift[HID];
    int tid = threadIdx.x;
    if (tid < HID) {
        float mu  = g_sum[tid] * (1.0f / N_NODES);
        float var = g_sumsq[tid] * (1.0f / N_NODES) - mu * mu;
        float sc  = gamma[tid] * rsqrtf(var + BN_EPS);
        s_scale[tid] = sc;
        s_shift[tid] = beta[tid] - mu * sc;
    }
    __syncthreads();
    int total4 = N_NODES * HID / 4;
    for (int i = blockIdx.x * blockDim.x + tid; i < total4;
         i += gridDim.x * blockDim.x) {
        int c = (i * 4) & (HID - 1);
        float4 v = ((const float4*)t)[i];
        v.x = fmaxf(v.x * s_scale[c + 0] + s_shift[c + 0], 0.f);
        v.y = fmaxf(v.y * s_scale[c + 1] + s_shift[c + 1], 0.f);
        v.z = fmaxf(v.z * s_scale[c + 2] + s_shift[c + 2], 0.f);
        v.w = fmaxf(v.w * s_scale[c + 3] + s_shift[c + 3], 0.f);
        if (add_res) {
            float4 r = ((const float4*)h)[i];
            v.x += r.x; v.y += r.y; v.z += r.z; v.w += r.w;
        }
        ((float4*)h)[i] = v;
    }
}

// ---------------- output projection: [N,128] @ [128,10] + b ------------------
__global__ __launch_bounds__(256)
void out_kernel(const float* __restrict__ h, const float* __restrict__ Wo,
                const float* __restrict__ bo, float* __restrict__ out) {
    __shared__ float ws[HID * OUT_DIM];
    __shared__ float bs[OUT_DIM];
    for (int i = threadIdx.x; i < HID * OUT_DIM; i += blockDim.x) ws[i] = Wo[i];
    if (threadIdx.x < OUT_DIM) bs[threadIdx.x] = bo[threadIdx.x];
    __syncthreads();
    int n = blockIdx.x * blockDim.x + threadIdx.x;
    if (n >= N_NODES) return;
    float acc[OUT_DIM];
    #pragma unroll
    for (int o = 0; o < OUT_DIM; o++) acc[o] = bs[o];
    const float4* hp = (const float4*)(h + n * HID);
    #pragma unroll 4
    for (int k4 = 0; k4 < HID / 4; k4++) {
        float4 v = hp[k4];
        int kb = k4 * 4;
        #pragma unroll
        for (int o = 0; o < OUT_DIM; o++) {
            acc[o] += v.x * ws[(kb + 0) * OUT_DIM + o]
                    + v.y * ws[(kb + 1) * OUT_DIM + o]
                    + v.z * ws[(kb + 2) * OUT_DIM + o]
                    + v.w * ws[(kb + 3) * OUT_DIM + o];
        }
    }
    #pragma unroll
    for (int o = 0; o < OUT_DIM; o++) out[n * OUT_DIM + o] = acc[o];
}

// ---------------- launch ----------------
extern "C" void kernel_launch(void* const* d_in, const int* in_sizes, int n_in,
                              void* d_out, int out_size) {
    const float* x     = (const float*)d_in[0];
    const void*  ei    = d_in[1];
    const float* W_in  = (const float*)d_in[2];
    const float* b_in  = (const float*)d_in[3];
    const float* Wc    = (const float*)d_in[4];
    const float* bc    = (const float*)d_in[5];
    const float* gamma = (const float*)d_in[6];
    const float* beta  = (const float*)d_in[7];
    const float* W_out = (const float*)d_in[8];
    const float* b_out = (const float*)d_in[9];
    float* out = (float*)d_out;

    float *p_h, *p_hw, *p_t;
    cudaGetSymbolAddress((void**)&p_h,  g_h);
    cudaGetSymbolAddress((void**)&p_hw, g_hw);
    cudaGetSymbolAddress((void**)&p_t,  g_t);

    detect_kernel<<<1, 256>>>(ei);
    zero_deg_kernel<<<98, 512>>>();
    count_deg_kernel<<<586, 1024>>>(ei);
    scan_kernel<<<1, SCAN_THREADS>>>();
    build_csr_kernel<<<586, 1024>>>(ei);

    // input layer: h = relu(x @ W_in + b_in)
    gemm_tf32_kernel<<<(N_NODES + 127) / 128, 256>>>(x, W_in, b_in, p_h,
                                                     N_NODES, IN_DIM, 1);

    for (int i = 0; i < 3; i++) {
        gemm_tf32_kernel<<<(N_NODES + 127) / 128, 256>>>(p_h, Wc + i * HID * HID,
                                                         nullptr, p_hw, N_NODES, HID, 0);
        zero_stats_kernel<<<1, 128>>>();
        agg_kernel<<<N_NODES / 8, 256>>>(p_hw, bc + i * HID, p_t);
        bn_apply_kernel<<<1024, 256>>>(p_t, p_h, gamma + i * HID, beta + i * HID, i > 0);
    }

    out_kernel<<<(N_NODES + 255) / 256, 256>>>(p_h, W_out, b_out, out);
}

// round 3
// speedup vs baseline: 1.3887x; 1.2396x over previous
#include <cuda_runtime.h>
#include <math.h>

#define N_NODES 50000
#define N_EDGES 600000
#define IN_DIM 256
#define HID 128
#define OUT_DIM 10
#define BN_EPS 1e-5f

#define SCAN_TILE 1024
#define N_TILES ((N_NODES + SCAN_TILE - 1) / SCAN_TILE)  // 49

// ---------------- scratch (static __device__ — no allocations) ----------------
__device__ float g_h[N_NODES * HID];      // activations
__device__ float g_hw[N_NODES * HID];     // h @ Wc
__device__ float g_t[N_NODES * HID];      // conv output (pre-BN)
__device__ int   g_deg[N_NODES];
__device__ int   g_rowptr[N_NODES + 1];
__device__ int   g_cursor[N_NODES];
__device__ float g_dinv[N_NODES];
__device__ int   g_csr_src[N_EDGES];
__device__ float g_csr_w[N_EDGES];        // dinv[src] per edge
__device__ float g_sum[HID];
__device__ float g_sumsq[HID];
__device__ int   g_tilesum[N_TILES];
__device__ int   g_tileoff[N_TILES + 1];
__device__ int   g_is64;

// ---------------- edge dtype detection (jax int64 vs silent int32) ------------
__global__ void detect_kernel(const void* ei) {
    __shared__ int bad;
    if (threadIdx.x == 0) bad = 0;
    __syncthreads();
    const long long* p = (const long long*)ei;
    for (int i = threadIdx.x; i < 4096; i += blockDim.x) {
        long long v = p[i];
        if (v < 0 || v >= N_NODES) atomicExch(&bad, 1);
    }
    __syncthreads();
    if (threadIdx.x == 0) g_is64 = bad ? 0 : 1;
}

__device__ __forceinline__ void load_edge(const void* ei, int e, int& s, int& d) {
    if (g_is64) {
        const long long* p = (const long long*)ei;
        s = (int)p[e];
        d = (int)p[N_EDGES + e];
    } else {
        const int* p = (const int*)ei;
        s = p[e];
        d = p[N_EDGES + e];
    }
}

// ---------------- CSR build ----------------
__global__ void zero_deg_kernel() {
    for (int i = blockIdx.x * blockDim.x + threadIdx.x; i < N_NODES;
         i += gridDim.x * blockDim.x)
        g_deg[i] = 0;
}

__global__ void count_deg_kernel(const void* ei) {
    for (int e = blockIdx.x * blockDim.x + threadIdx.x; e < N_EDGES;
         e += gridDim.x * blockDim.x) {
        int s, d;
        load_edge(ei, e, s, d);
        atomicAdd(&g_deg[d], 1);
    }
}

// ---- 3-phase coalesced multi-block scan ----
__global__ __launch_bounds__(SCAN_TILE)
void tile_sum_kernel() {
    __shared__ int wsum[32];
    int tid = threadIdx.x, lane = tid & 31, wid = tid >> 5;
    int i = blockIdx.x * SCAN_TILE + tid;
    int d = (i < N_NODES) ? g_deg[i] : 0;
    int v = d;
    #pragma unroll
    for (int off = 16; off > 0; off >>= 1)
        v += __shfl_down_sync(0xffffffffu, v, off);
    if (lane == 0) wsum[wid] = v;
    __syncthreads();
    if (wid == 0) {
        int t2 = wsum[lane];
        #pragma unroll
        for (int off = 16; off > 0; off >>= 1)
            t2 += __shfl_down_sync(0xffffffffu, t2, off);
        if (lane == 0) g_tilesum[blockIdx.x] = t2;
    }
}

__global__ void tile_scan_kernel() {
    // single warp: exclusive scan of N_TILES (=49) tile sums
    int lane = threadIdx.x;
    int run = 0;
    for (int base = 0; base < N_TILES; base += 32) {
        int idx = base + lane;
        int v = (idx < N_TILES) ? g_tilesum[idx] : 0;
        int incl = v;
        #pragma unroll
        for (int off = 1; off < 32; off <<= 1) {
            int t2 = __shfl_up_sync(0xffffffffu, incl, off);
            if (lane >= off) incl += t2;
        }
        if (idx <= N_TILES) { /* write exclusive */ }
        if (idx < N_TILES) g_tileoff[idx] = run + incl - v;
        int tot = __shfl_sync(0xffffffffu, incl, 31);
        run += tot;
    }
    if (lane == 0) g_tileoff[N_TILES] = run;
}

__global__ __launch_bounds__(SCAN_TILE)
void tile_write_kernel() {
    __shared__ int wsum[32];
    int tid = threadIdx.x, lane = tid & 31, wid = tid >> 5;
    int i = blockIdx.x * SCAN_TILE + tid;
    int d = (i < N_NODES) ? g_deg[i] : 0;
    int incl = d;
    #pragma unroll
    for (int off = 1; off < 32; off <<= 1) {
        int v = __shfl_up_sync(0xffffffffu, incl, off);
        if (lane >= off) incl += v;
    }
    if (lane == 31) wsum[wid] = incl;
    __syncthreads();
    if (wid == 0) {
        int v = wsum[lane];
        int wi = v;
        #pragma unroll
        for (int off = 1; off < 32; off <<= 1) {
            int t2 = __shfl_up_sync(0xffffffffu, wi, off);
            if (lane >= off) wi += t2;
        }
        wsum[lane] = wi - v;  // exclusive warp offsets
    }
    __syncthreads();
    int excl = g_tileoff[blockIdx.x] + wsum[wid] + incl - d;
    if (i < N_NODES) {
        g_rowptr[i] = excl;
        g_cursor[i] = excl;
        g_dinv[i]   = rsqrtf((float)d + 1.0f);
    }
    if (i == N_NODES - 1) g_rowptr[N_NODES] = g_tileoff[N_TILES];
}

__global__ void build_csr_kernel(const void* ei) {
    for (int e = blockIdx.x * blockDim.x + threadIdx.x; e < N_EDGES;
         e += gridDim.x * blockDim.x) {
        int s, d;
        load_edge(ei, e, s, d);
        int pos = atomicAdd(&g_cursor[d], 1);
        g_csr_src[pos] = s;
        g_csr_w[pos]   = g_dinv[s];
    }
}

// ---------------- tf32 tensor-core GEMM ----------------
// C[N x 128] = A[N x K] @ W[K x 128] (+bias, relu)
// block: 256 thr = 8 warps; block tile 128(M) x 128(N); warp tile 64(M) x 32(N)
// mma.sync.aligned.m16n8k8.row.col.f32.tf32.tf32.f32

__device__ __forceinline__ unsigned f2tf32(float f) {
    unsigned r;
    asm("cvt.rna.tf32.f32 %0, %1;" : "=r"(r) : "f"(f));
    return r;
}

#define APAD 36   // As row stride: banks = m*4 + k -> conflict-free
#define BPAD 136  // Bs row stride: banks = k*8 + n -> conflict-free

__global__ __launch_bounds__(256)
void gemm_tf32_kernel(const float* __restrict__ A, const float* __restrict__ W,
                      const float* __restrict__ bias, float* __restrict__ C,
                      int N, int K, int do_relu) {
    __shared__ unsigned As[128 * APAD];  // [m][k] tf32 bits
    __shared__ unsigned Bs[32 * BPAD];   // [k][n] tf32 bits

    int tid = threadIdx.x;
    int w = tid >> 5, lane = tid & 31;
    int wm = (w & 1) * 64;      // warp M origin within block tile
    int wn = (w >> 1) * 32;     // warp N origin
    int gid = lane >> 2, tig = lane & 3;
    int row0 = blockIdx.x * 128;

    float acc[4][4][4];  // [matom][natom][c0..c3]
    #pragma unroll
    for (int i = 0; i < 4; i++)
        #pragma unroll
        for (int j = 0; j < 4; j++)
            #pragma unroll
            for (int c = 0; c < 4; c++) acc[i][j][c] = 0.f;

    for (int k0 = 0; k0 < K; k0 += 32) {
        // stage A tile: 128 x 32
        #pragma unroll
        for (int p = 0; p < 4; p++) {
            int r  = p * 32 + (tid >> 3);
            int kk = (tid & 7) * 4;
            int grow = row0 + r;
            float4 v = make_float4(0.f, 0.f, 0.f, 0.f);
            if (grow < N) v = *(const float4*)&A[(size_t)grow * K + k0 + kk];
            unsigned* dst = &As[r * APAD + kk];
            dst[0] = f2tf32(v.x); dst[1] = f2tf32(v.y);
            dst[2] = f2tf32(v.z); dst[3] = f2tf32(v.w);
        }
        // stage W tile: 32 x 128
        #pragma unroll
        for (int p = 0; p < 4; p++) {
            int kk = p * 8 + (tid >> 5);
            int c  = (tid & 31) * 4;
            float4 v = *(const float4*)&W[(size_t)(k0 + kk) * HID + c];
            unsigned* dst = &Bs[kk * BPAD + c];
            dst[0] = f2tf32(v.x); dst[1] = f2tf32(v.y);
            dst[2] = f2tf32(v.z); dst[3] = f2tf32(v.w);
        }
        __syncthreads();

        #pragma unroll
        for (int ks = 0; ks < 4; ks++) {
            int k = ks * 8;
            unsigned afr[4][4], bfr[4][2];
            #pragma unroll
            for (int i = 0; i < 4; i++) {
                int m = wm + i * 16;
                afr[i][0] = As[(m + gid)     * APAD + k + tig];
                afr[i][1] = As[(m + gid + 8) * APAD + k + tig];
                afr[i][2] = As[(m + gid)     * APAD + k + tig + 4];
                afr[i][3] = As[(m + gid + 8) * APAD + k + tig + 4];
            }
            #pragma unroll
            for (int j = 0; j < 4; j++) {
                int n = wn + j * 8 + gid;
                bfr[j][0] = Bs[(k + tig)     * BPAD + n];
                bfr[j][1] = Bs[(k + tig + 4) * BPAD + n];
            }
            #pragma unroll
            for (int i = 0; i < 4; i++)
                #pragma unroll
                for (int j = 0; j < 4; j++) {
                    asm volatile(
                        "mma.sync.aligned.m16n8k8.row.col.f32.tf32.tf32.f32 "
                        "{%0,%1,%2,%3}, {%4,%5,%6,%7}, {%8,%9}, {%0,%1,%2,%3};"
                        : "+f"(acc[i][j][0]), "+f"(acc[i][j][1]),
                          "+f"(acc[i][j][2]), "+f"(acc[i][j][3])
                        : "r"(afr[i][0]), "r"(afr[i][1]),
                          "r"(afr[i][2]), "r"(afr[i][3]),
                          "r"(bfr[j][0]), "r"(bfr[j][1]));
                }
        }
        __syncthreads();
    }

    // epilogue: c0/c1 at (m+gid, n+2*tig(+1)), c2/c3 at (m+gid+8, ...)
    #pragma unroll
    for (int i = 0; i < 4; i++) {
        int r_up = row0 + wm + i * 16 + gid;
        int r_dn = r_up + 8;
        #pragma unroll
        for (int j = 0; j < 4; j++) {
            int col = wn + j * 8 + 2 * tig;
            float b0 = bias ? bias[col]     : 0.f;
            float b1 = bias ? bias[col + 1] : 0.f;
            float u0 = acc[i][j][0] + b0, u1 = acc[i][j][1] + b1;
            float d0 = acc[i][j][2] + b0, d1 = acc[i][j][3] + b1;
            if (do_relu) {
                u0 = fmaxf(u0, 0.f); u1 = fmaxf(u1, 0.f);
                d0 = fmaxf(d0, 0.f); d1 = fmaxf(d1, 0.f);
            }
            if (r_up < N) *(float2*)&C[(size_t)r_up * HID + col] = make_float2(u0, u1);
            if (r_dn < N) *(float2*)&C[(size_t)r_dn * HID + col] = make_float2(d0, d1);
        }
    }
}

// ---------------- per-layer: zero BN stats ----------------
__global__ void zero_stats_kernel() {
    int i = threadIdx.x;
    if (i < HID) { g_sum[i] = 0.f; g_sumsq[i] = 0.f; }
}

// ---------------- aggregation (gather CSR) + self-loop + bias + BN stats ------
__global__ __launch_bounds__(256)
void agg_kernel(const float* __restrict__ hw, const float* __restrict__ bc,
                float* __restrict__ t) {
    __shared__ float s_sum[HID], s_sq[HID];
    int tid = threadIdx.x;
    if (tid < HID) { s_sum[tid] = 0.f; s_sq[tid] = 0.f; }
    __syncthreads();

    int lane = tid & 31;
    int n = blockIdx.x * 8 + (tid >> 5);
    if (n < N_NODES) {
        int e0 = g_rowptr[n], e1 = g_rowptr[n + 1];
        float a0 = 0.f, a1 = 0.f, a2 = 0.f, a3 = 0.f;
        int e = e0;
        int s_next = 0; float w_next = 0.f;
        if (e < e1) { s_next = __ldg(&g_csr_src[e]); w_next = __ldg(&g_csr_w[e]); }
        while (e < e1) {
            int s = s_next; float w = w_next;
            e++;
            if (e < e1) { s_next = __ldg(&g_csr_src[e]); w_next = __ldg(&g_csr_w[e]); }
            float4 v = *(const float4*)(hw + s * HID + lane * 4);
            a0 += v.x * w; a1 += v.y * w; a2 += v.z * w; a3 += v.w * w;
        }
        float di  = g_dinv[n];
        float dii = di * di;
        int c = lane * 4;
        float4 sv = *(const float4*)(hw + n * HID + c);
        float t0 = a0 * di + sv.x * dii + bc[c + 0];
        float t1 = a1 * di + sv.y * dii + bc[c + 1];
        float t2 = a2 * di + sv.z * dii + bc[c + 2];
        float t3 = a3 * di + sv.w * dii + bc[c + 3];
        *(float4*)(t + n * HID + c) = make_float4(t0, t1, t2, t3);
        atomicAdd(&s_sum[c + 0], t0); atomicAdd(&s_sq[c + 0], t0 * t0);
        atomicAdd(&s_sum[c + 1], t1); atomicAdd(&s_sq[c + 1], t1 * t1);
        atomicAdd(&s_sum[c + 2], t2); atomicAdd(&s_sq[c + 2], t2 * t2);
        atomicAdd(&s_sum[c + 3], t3); atomicAdd(&s_sq[c + 3], t3 * t3);
    }
    __syncthreads();
    if (tid < HID) {
        atomicAdd(&g_sum[tid],   s_sum[tid]);
        atomicAdd(&g_sumsq[tid], s_sq[tid]);
    }
}

// ---------------- BN apply + relu + residual ----------------
__global__ __launch_bounds__(256)
void bn_apply_kernel(const float* __restrict__ t, float* __restrict__ h,
                     const float* __restrict__ gamma, const float* __restrict__ beta,
                     int add_res) {
    __shared__ float s_scale[HID], s_shift[HID];
    int tid = threadIdx.x;
    if (tid < HID) {
        float mu  = g_sum[tid] * (1.0f / N_NODES);
        float var = g_sumsq[tid] * (1.0f / N_NODES) - mu * mu;
        float sc  = gamma[tid] * rsqrtf(var + BN_EPS);
        s_scale[tid] = sc;
        s_shift[tid] = beta[tid] - mu * sc;
    }
    __syncthreads();
    int total4 = N_NODES * HID / 4;
    for (int i = blockIdx.x * blockDim.x + tid; i < total4;
         i += gridDim.x * blockDim.x) {
        int c = (i * 4) & (HID - 1);
        float4 v = ((const float4*)t)[i];
        v.x = fmaxf(v.x * s_scale[c + 0] + s_shift[c + 0], 0.f);
        v.y = fmaxf(v.y * s_scale[c + 1] + s_shift[c + 1], 0.f);
        v.z = fmaxf(v.z * s_scale[c + 2] + s_shift[c + 2], 0.f);
        v.w = fmaxf(v.w * s_scale[c + 3] + s_shift[c + 3], 0.f);
        if (add_res) {
            float4 r = ((const float4*)h)[i];
            v.x += r.x; v.y += r.y; v.z += r.z; v.w += r.w;
        }
        ((float4*)h)[i] = v;
    }
}

// ---------------- output projection: [N,128] @ [128,10] + b ------------------
__global__ __launch_bounds__(256)
void out_kernel(const float* __restrict__ h, const float* __restrict__ Wo,
                const float* __restrict__ bo, float* __restrict__ out) {
    __shared__ float ws[HID * OUT_DIM];
    __shared__ float bs[OUT_DIM];
    for (int i = threadIdx.x; i < HID * OUT_DIM; i += blockDim.x) ws[i] = Wo[i];
    if (threadIdx.x < OUT_DIM) bs[threadIdx.x] = bo[threadIdx.x];
    __syncthreads();
    int n = blockIdx.x * blockDim.x + threadIdx.x;
    if (n >= N_NODES) return;
    float acc[OUT_DIM];
    #pragma unroll
    for (int o = 0; o < OUT_DIM; o++) acc[o] = bs[o];
    const float4* hp = (const float4*)(h + n * HID);
    #pragma unroll 4
    for (int k4 = 0; k4 < HID / 4; k4++) {
        float4 v = hp[k4];
        int kb = k4 * 4;
        #pragma unroll
        for (int o = 0; o < OUT_DIM; o++) {
            acc[o] += v.x * ws[(kb + 0) * OUT_DIM + o]
                    + v.y * ws[(kb + 1) * OUT_DIM + o]
                    + v.z * ws[(kb + 2) * OUT_DIM + o]
                    + v.w * ws[(kb + 3) * OUT_DIM + o];
        }
    }
    #pragma unroll
    for (int o = 0; o < OUT_DIM; o++) out[n * OUT_DIM + o] = acc[o];
}

// ---------------- launch ----------------
extern "C" void kernel_launch(void* const* d_in, const int* in_sizes, int n_in,
                              void* d_out, int out_size) {
    const float* x     = (const float*)d_in[0];
    const void*  ei    = d_in[1];
    const float* W_in  = (const float*)d_in[2];
    const float* b_in  = (const float*)d_in[3];
    const float* Wc    = (const float*)d_in[4];
    const float* bc    = (const float*)d_in[5];
    const float* gamma = (const float*)d_in[6];
    const float* beta  = (const float*)d_in[7];
    const float* W_out = (const float*)d_in[8];
    const float* b_out = (const float*)d_in[9];
    float* out = (float*)d_out;

    float *p_h, *p_hw, *p_t;
    cudaGetSymbolAddress((void**)&p_h,  g_h);
    cudaGetSymbolAddress((void**)&p_hw, g_hw);
    cudaGetSymbolAddress((void**)&p_t,  g_t);

    detect_kernel<<<1, 256>>>(ei);
    zero_deg_kernel<<<98, 512>>>();
    count_deg_kernel<<<586, 1024>>>(ei);
    tile_sum_kernel<<<N_TILES, SCAN_TILE>>>();
    tile_scan_kernel<<<1, 32>>>();
    tile_write_kernel<<<N_TILES, SCAN_TILE>>>();
    build_csr_kernel<<<586, 1024>>>(ei);

    // input layer: h = relu(x @ W_in + b_in)
    gemm_tf32_kernel<<<(N_NODES + 127) / 128, 256>>>(x, W_in, b_in, p_h,
                                                     N_NODES, IN_DIM, 1);

    for (int i = 0; i < 3; i++) {
        gemm_tf32_kernel<<<(N_NODES + 127) / 128, 256>>>(p_h, Wc + i * HID * HID,
                                                         nullptr, p_hw, N_NODES, HID, 0);
        zero_stats_kernel<<<1, 128>>>();
        agg_kernel<<<N_NODES / 8, 256>>>(p_hw, bc + i * HID, p_t);
        bn_apply_kernel<<<1024, 256>>>(p_t, p_h, gamma + i * HID, beta + i * HID, i > 0);
    }

    out_kernel<<<(N_NODES + 255) / 256, 256>>>(p_h, W_out, b_out, out);
}

// round 4
// speedup vs baseline: 1.7048x; 1.2276x over previous
#include <cuda_runtime.h>
#include <math.h>

#define N_NODES 50000
#define N_EDGES 600000
#define IN_DIM 256
#define HID 128
#define OUT_DIM 10
#define BN_EPS 1e-5f

#define SCAN_TILE 1024
#define N_TILES ((N_NODES + SCAN_TILE - 1) / SCAN_TILE)  // 49

// ---------------- scratch (static __device__ — no allocations) ----------------
__device__ float g_h[N_NODES * HID];      // activations
__device__ float g_hw[N_NODES * HID];     // h @ Wc
__device__ float g_t[N_NODES * HID];      // conv output (pre-BN)
__device__ int   g_deg[N_NODES];
__device__ int   g_rowptr[N_NODES + 1];
__device__ int   g_cursor[N_NODES];
__device__ float g_dinv[N_NODES];
__device__ int   g_csr_src[N_EDGES];
__device__ float g_csr_w[N_EDGES];        // dinv[src] per edge
__device__ float g_sum[3 * HID];          // per-layer BN stats
__device__ float g_sumsq[3 * HID];
__device__ int   g_tilesum[N_TILES];
__device__ int   g_tileoff[N_TILES + 1];
__device__ int   g_is64;

// -------- detect edge dtype (block 0) + zero deg + zero all BN stats ----------
__global__ void detect_zero_kernel(const void* ei) {
    if (blockIdx.x == 0) {
        __shared__ int bad;
        if (threadIdx.x == 0) bad = 0;
        __syncthreads();
        const long long* p = (const long long*)ei;
        for (int i = threadIdx.x; i < 4096; i += blockDim.x) {
            long long v = p[i];
            if (v < 0 || v >= N_NODES) atomicExch(&bad, 1);
        }
        __syncthreads();
        if (threadIdx.x == 0) g_is64 = bad ? 0 : 1;
        if (threadIdx.x < 3 * HID) {
            g_sum[threadIdx.x] = 0.f;
            g_sumsq[threadIdx.x] = 0.f;
        }
    }
    for (int i = blockIdx.x * blockDim.x + threadIdx.x; i < N_NODES;
         i += gridDim.x * blockDim.x)
        g_deg[i] = 0;
}

__device__ __forceinline__ void load_edge(const void* ei, int e, int& s, int& d) {
    if (g_is64) {
        const long long* p = (const long long*)ei;
        s = (int)p[e];
        d = (int)p[N_EDGES + e];
    } else {
        const int* p = (const int*)ei;
        s = p[e];
        d = p[N_EDGES + e];
    }
}

__global__ void count_deg_kernel(const void* ei) {
    for (int e = blockIdx.x * blockDim.x + threadIdx.x; e < N_EDGES;
         e += gridDim.x * blockDim.x) {
        int s, d;
        load_edge(ei, e, s, d);
        atomicAdd(&g_deg[d], 1);
    }
}

// ---- 3-phase coalesced multi-block scan ----
__global__ __launch_bounds__(SCAN_TILE)
void tile_sum_kernel() {
    __shared__ int wsum[32];
    int tid = threadIdx.x, lane = tid & 31, wid = tid >> 5;
    int i = blockIdx.x * SCAN_TILE + tid;
    int d = (i < N_NODES) ? g_deg[i] : 0;
    int v = d;
    #pragma unroll
    for (int off = 16; off > 0; off >>= 1)
        v += __shfl_down_sync(0xffffffffu, v, off);
    if (lane == 0) wsum[wid] = v;
    __syncthreads();
    if (wid == 0) {
        int t2 = wsum[lane];
        #pragma unroll
        for (int off = 16; off > 0; off >>= 1)
            t2 += __shfl_down_sync(0xffffffffu, t2, off);
        if (lane == 0) g_tilesum[blockIdx.x] = t2;
    }
}

__global__ void tile_scan_kernel() {
    int lane = threadIdx.x;
    int run = 0;
    for (int base = 0; base < N_TILES; base += 32) {
        int idx = base + lane;
        int v = (idx < N_TILES) ? g_tilesum[idx] : 0;
        int incl = v;
        #pragma unroll
        for (int off = 1; off < 32; off <<= 1) {
            int t2 = __shfl_up_sync(0xffffffffu, incl, off);
            if (lane >= off) incl += t2;
        }
        if (idx < N_TILES) g_tileoff[idx] = run + incl - v;
        int tot = __shfl_sync(0xffffffffu, incl, 31);
        run += tot;
    }
    if (lane == 0) g_tileoff[N_TILES] = run;
}

__global__ __launch_bounds__(SCAN_TILE)
void tile_write_kernel() {
    __shared__ int wsum[32];
    int tid = threadIdx.x, lane = tid & 31, wid = tid >> 5;
    int i = blockIdx.x * SCAN_TILE + tid;
    int d = (i < N_NODES) ? g_deg[i] : 0;
    int incl = d;
    #pragma unroll
    for (int off = 1; off < 32; off <<= 1) {
        int v = __shfl_up_sync(0xffffffffu, incl, off);
        if (lane >= off) incl += v;
    }
    if (lane == 31) wsum[wid] = incl;
    __syncthreads();
    if (wid == 0) {
        int v = wsum[lane];
        int wi = v;
        #pragma unroll
        for (int off = 1; off < 32; off <<= 1) {
            int t2 = __shfl_up_sync(0xffffffffu, wi, off);
            if (lane >= off) wi += t2;
        }
        wsum[lane] = wi - v;
    }
    __syncthreads();
    int excl = g_tileoff[blockIdx.x] + wsum[wid] + incl - d;
    if (i < N_NODES) {
        g_rowptr[i] = excl;
        g_cursor[i] = excl;
        g_dinv[i]   = rsqrtf((float)d + 1.0f);
    }
    if (i == N_NODES - 1) g_rowptr[N_NODES] = g_tileoff[N_TILES];
}

__global__ void build_csr_kernel(const void* ei) {
    for (int e = blockIdx.x * blockDim.x + threadIdx.x; e < N_EDGES;
         e += gridDim.x * blockDim.x) {
        int s, d;
        load_edge(ei, e, s, d);
        int pos = atomicAdd(&g_cursor[d], 1);
        g_csr_src[pos] = s;
        g_csr_w[pos]   = g_dinv[s];
    }
}

// ---------------- tf32 tensor-core GEMM (optionally fused BN+relu+res on A) ---
__device__ __forceinline__ unsigned f2tf32(float f) {
    unsigned r;
    asm("cvt.rna.tf32.f32 %0, %1;" : "=r"(r) : "f"(f));
    return r;
}

#define APAD 36
#define BPAD 136

// If t_in != nullptr: A[r][k] = relu(t_in[r][k]*sc[k]+sh[k]) (+ hres[r][k] if add_res),
// and the computed activation is written back to h_out. Otherwise A = A_in.
__global__ __launch_bounds__(256)
void gemm_tf32_kernel(const float* __restrict__ A_in, const float* __restrict__ W,
                      const float* __restrict__ bias, float* __restrict__ C,
                      int N, int K, int do_relu,
                      const float* __restrict__ t_in,
                      const float* __restrict__ st_sum, const float* __restrict__ st_sq,
                      const float* __restrict__ gma, const float* __restrict__ bta,
                      const float* __restrict__ hres, float* __restrict__ h_out,
                      int add_res) {
    __shared__ unsigned As[128 * APAD];
    __shared__ unsigned Bs[32 * BPAD];
    __shared__ float s_sc[HID], s_sh[HID];

    int tid = threadIdx.x;
    int w = tid >> 5, lane = tid & 31;
    int wm = (w & 1) * 64;
    int wn = (w >> 1) * 32;
    int gid = lane >> 2, tig = lane & 3;
    int row0 = blockIdx.x * 128;

    if (t_in && tid < HID) {
        float mu  = st_sum[tid] * (1.0f / N_NODES);
        float var = st_sq[tid] * (1.0f / N_NODES) - mu * mu;
        float sc  = gma[tid] * rsqrtf(var + BN_EPS);
        s_sc[tid] = sc;
        s_sh[tid] = bta[tid] - mu * sc;
    }
    __syncthreads();

    float acc[4][4][4];
    #pragma unroll
    for (int i = 0; i < 4; i++)
        #pragma unroll
        for (int j = 0; j < 4; j++)
            #pragma unroll
            for (int c = 0; c < 4; c++) acc[i][j][c] = 0.f;

    for (int k0 = 0; k0 < K; k0 += 32) {
        // stage A tile 128x32
        #pragma unroll
        for (int p = 0; p < 4; p++) {
            int r  = p * 32 + (tid >> 3);
            int kk = (tid & 7) * 4;
            int grow = row0 + r;
            float4 v = make_float4(0.f, 0.f, 0.f, 0.f);
            if (grow < N) {
                size_t off = (size_t)grow * K + k0 + kk;
                if (t_in) {
                    int c = k0 + kk;
                    float4 tv = *(const float4*)&t_in[off];
                    v.x = fmaxf(tv.x * s_sc[c + 0] + s_sh[c + 0], 0.f);
                    v.y = fmaxf(tv.y * s_sc[c + 1] + s_sh[c + 1], 0.f);
                    v.z = fmaxf(tv.z * s_sc[c + 2] + s_sh[c + 2], 0.f);
                    v.w = fmaxf(tv.w * s_sc[c + 3] + s_sh[c + 3], 0.f);
                    if (add_res) {
                        float4 rv = *(const float4*)&hres[off];
                        v.x += rv.x; v.y += rv.y; v.z += rv.z; v.w += rv.w;
                    }
                    *(float4*)&h_out[off] = v;
                } else {
                    v = *(const float4*)&A_in[off];
                }
            }
            unsigned* dst = &As[r * APAD + kk];
            dst[0] = f2tf32(v.x); dst[1] = f2tf32(v.y);
            dst[2] = f2tf32(v.z); dst[3] = f2tf32(v.w);
        }
        // stage W tile 32x128
        #pragma unroll
        for (int p = 0; p < 4; p++) {
            int kk = p * 8 + (tid >> 5);
            int c  = (tid & 31) * 4;
            float4 v = *(const float4*)&W[(size_t)(k0 + kk) * HID + c];
            unsigned* dst = &Bs[kk * BPAD + c];
            dst[0] = f2tf32(v.x); dst[1] = f2tf32(v.y);
            dst[2] = f2tf32(v.z); dst[3] = f2tf32(v.w);
        }
        __syncthreads();

        #pragma unroll
        for (int ks = 0; ks < 4; ks++) {
            int k = ks * 8;
            unsigned afr[4][4], bfr[4][2];
            #pragma unroll
            for (int i = 0; i < 4; i++) {
                int m = wm + i * 16;
                afr[i][0] = As[(m + gid)     * APAD + k + tig];
                afr[i][1] = As[(m + gid + 8) * APAD + k + tig];
                afr[i][2] = As[(m + gid)     * APAD + k + tig + 4];
                afr[i][3] = As[(m + gid + 8) * APAD + k + tig + 4];
            }
            #pragma unroll
            for (int j = 0; j < 4; j++) {
                int n = wn + j * 8 + gid;
                bfr[j][0] = Bs[(k + tig)     * BPAD + n];
                bfr[j][1] = Bs[(k + tig + 4) * BPAD + n];
            }
            #pragma unroll
            for (int i = 0; i < 4; i++)
                #pragma unroll
                for (int j = 0; j < 4; j++) {
                    asm volatile(
                        "mma.sync.aligned.m16n8k8.row.col.f32.tf32.tf32.f32 "
                        "{%0,%1,%2,%3}, {%4,%5,%6,%7}, {%8,%9}, {%0,%1,%2,%3};"
                        : "+f"(acc[i][j][0]), "+f"(acc[i][j][1]),
                          "+f"(acc[i][j][2]), "+f"(acc[i][j][3])
                        : "r"(afr[i][0]), "r"(afr[i][1]),
                          "r"(afr[i][2]), "r"(afr[i][3]),
                          "r"(bfr[j][0]), "r"(bfr[j][1]));
                }
        }
        __syncthreads();
    }

    #pragma unroll
    for (int i = 0; i < 4; i++) {
        int r_up = row0 + wm + i * 16 + gid;
        int r_dn = r_up + 8;
        #pragma unroll
        for (int j = 0; j < 4; j++) {
            int col = wn + j * 8 + 2 * tig;
            float b0 = bias ? bias[col]     : 0.f;
            float b1 = bias ? bias[col + 1] : 0.f;
            float u0 = acc[i][j][0] + b0, u1 = acc[i][j][1] + b1;
            float d0 = acc[i][j][2] + b0, d1 = acc[i][j][3] + b1;
            if (do_relu) {
                u0 = fmaxf(u0, 0.f); u1 = fmaxf(u1, 0.f);
                d0 = fmaxf(d0, 0.f); d1 = fmaxf(d1, 0.f);
            }
            if (r_up < N) *(float2*)&C[(size_t)r_up * HID + col] = make_float2(u0, u1);
            if (r_dn < N) *(float2*)&C[(size_t)r_dn * HID + col] = make_float2(d0, d1);
        }
    }
}

// ---------------- aggregation (gather CSR) + self-loop + bias + BN stats ------
__global__ __launch_bounds__(256)
void agg_kernel(const float* __restrict__ hw, const float* __restrict__ bc,
                float* __restrict__ t, float* __restrict__ st_sum,
                float* __restrict__ st_sq) {
    __shared__ float s_sum[HID], s_sq[HID];
    int tid = threadIdx.x;
    if (tid < HID) { s_sum[tid] = 0.f; s_sq[tid] = 0.f; }
    __syncthreads();

    int lane = tid & 31;
    int n = blockIdx.x * 8 + (tid >> 5);
    if (n < N_NODES) {
        int e0 = g_rowptr[n], e1 = g_rowptr[n + 1];
        float a0 = 0.f, a1 = 0.f, a2 = 0.f, a3 = 0.f;
        int e = e0;
        int s0 = 0, s1 = 0; float w0 = 0.f, w1 = 0.f;
        if (e < e1)     { s0 = __ldg(&g_csr_src[e]);     w0 = __ldg(&g_csr_w[e]); }
        if (e + 1 < e1) { s1 = __ldg(&g_csr_src[e + 1]); w1 = __ldg(&g_csr_w[e + 1]); }
        while (e < e1) {
            int s = s0; float w = w0;
            s0 = s1; w0 = w1;
            if (e + 2 < e1) { s1 = __ldg(&g_csr_src[e + 2]); w1 = __ldg(&g_csr_w[e + 2]); }
            float4 v = *(const float4*)(hw + s * HID + lane * 4);
            a0 += v.x * w; a1 += v.y * w; a2 += v.z * w; a3 += v.w * w;
            e++;
        }
        float di  = g_dinv[n];
        float dii = di * di;
        int c = lane * 4;
        float4 sv = *(const float4*)(hw + n * HID + c);
        float t0 = a0 * di + sv.x * dii + bc[c + 0];
        float t1 = a1 * di + sv.y * dii + bc[c + 1];
        float t2 = a2 * di + sv.z * dii + bc[c + 2];
        float t3 = a3 * di + sv.w * dii + bc[c + 3];
        *(float4*)(t + n * HID + c) = make_float4(t0, t1, t2, t3);
        atomicAdd(&s_sum[c + 0], t0); atomicAdd(&s_sq[c + 0], t0 * t0);
        atomicAdd(&s_sum[c + 1], t1); atomicAdd(&s_sq[c + 1], t1 * t1);
        atomicAdd(&s_sum[c + 2], t2); atomicAdd(&s_sq[c + 2], t2 * t2);
        atomicAdd(&s_sum[c + 3], t3); atomicAdd(&s_sq[c + 3], t3 * t3);
    }
    __syncthreads();
    if (tid < HID) {
        atomicAdd(&st_sum[tid], s_sum[tid]);
        atomicAdd(&st_sq[tid],  s_sq[tid]);
    }
}

// ------- output projection fused with final BN+relu+residual ------------------
// out = (relu(bn(t)) + hres) @ W_out + b_out
__global__ __launch_bounds__(256)
void out_kernel(const float* __restrict__ t, const float* __restrict__ hres,
                const float* __restrict__ st_sum, const float* __restrict__ st_sq,
                const float* __restrict__ gma, const float* __restrict__ bta,
                const float* __restrict__ Wo, const float* __restrict__ bo,
                float* __restrict__ out) {
    __shared__ float ws[HID * OUT_DIM];
    __shared__ float bs[OUT_DIM];
    __shared__ float s_sc[HID], s_sh[HID];
    int tid = threadIdx.x;
    for (int i = tid; i < HID * OUT_DIM; i += blockDim.x) ws[i] = Wo[i];
    if (tid < OUT_DIM) bs[tid] = bo[tid];
    if (tid < HID) {
        float mu  = st_sum[tid] * (1.0f / N_NODES);
        float var = st_sq[tid] * (1.0f / N_NODES) - mu * mu;
        float sc  = gma[tid] * rsqrtf(var + BN_EPS);
        s_sc[tid] = sc;
        s_sh[tid] = bta[tid] - mu * sc;
    }
    __syncthreads();
    int n = blockIdx.x * blockDim.x + tid;
    if (n >= N_NODES) return;
    float acc[OUT_DIM];
    #pragma unroll
    for (int o = 0; o < OUT_DIM; o++) acc[o] = bs[o];
    const float4* tp = (const float4*)(t + (size_t)n * HID);
    const float4* rp = (const float4*)(hres + (size_t)n * HID);
    #pragma unroll 4
    for (int k4 = 0; k4 < HID / 4; k4++) {
        float4 tv = tp[k4];
        float4 rv = rp[k4];
        int kb = k4 * 4;
        float a0 = fmaxf(tv.x * s_sc[kb + 0] + s_sh[kb + 0], 0.f) + rv.x;
        float a1 = fmaxf(tv.y * s_sc[kb + 1] + s_sh[kb + 1], 0.f) + rv.y;
        float a2 = fmaxf(tv.z * s_sc[kb + 2] + s_sh[kb + 2], 0.f) + rv.z;
        float a3 = fmaxf(tv.w * s_sc[kb + 3] + s_sh[kb + 3], 0.f) + rv.w;
        #pragma unroll
        for (int o = 0; o < OUT_DIM; o++) {
            acc[o] += a0 * ws[(kb + 0) * OUT_DIM + o]
                    + a1 * ws[(kb + 1) * OUT_DIM + o]
                    + a2 * ws[(kb + 2) * OUT_DIM + o]
                    + a3 * ws[(kb + 3) * OUT_DIM + o];
        }
    }
    #pragma unroll
    for (int o = 0; o < OUT_DIM; o++) out[n * OUT_DIM + o] = acc[o];
}

// ---------------- launch ----------------
extern "C" void kernel_launch(void* const* d_in, const int* in_sizes, int n_in,
                              void* d_out, int out_size) {
    const float* x     = (const float*)d_in[0];
    const void*  ei    = d_in[1];
    const float* W_in  = (const float*)d_in[2];
    const float* b_in  = (const float*)d_in[3];
    const float* Wc    = (const float*)d_in[4];
    const float* bc    = (const float*)d_in[5];
    const float* gamma = (const float*)d_in[6];
    const float* beta  = (const float*)d_in[7];
    const float* W_out = (const float*)d_in[8];
    const float* b_out = (const float*)d_in[9];
    float* out = (float*)d_out;

    float *p_h, *p_hw, *p_t, *p_sum, *p_sq;
    cudaGetSymbolAddress((void**)&p_h,   g_h);
    cudaGetSymbolAddress((void**)&p_hw,  g_hw);
    cudaGetSymbolAddress((void**)&p_t,   g_t);
    cudaGetSymbolAddress((void**)&p_sum, g_sum);
    cudaGetSymbolAddress((void**)&p_sq,  g_sumsq);

    static cudaStream_t s_side = nullptr;
    static cudaEvent_t ev_fork = nullptr, ev_join = nullptr;
    if (!s_side) {
        cudaStreamCreateWithFlags(&s_side, cudaStreamNonBlocking);
        cudaEventCreateWithFlags(&ev_fork, cudaEventDisableTiming);
        cudaEventCreateWithFlags(&ev_join, cudaEventDisableTiming);
    }

    // fork: CSR build on side stream, overlapped with input + layer-0 GEMMs
    cudaEventRecord(ev_fork, 0);
    cudaStreamWaitEvent(s_side, ev_fork, 0);
    detect_zero_kernel<<<99, 512, 0, s_side>>>(ei);
    count_deg_kernel<<<586, 1024, 0, s_side>>>(ei);
    tile_sum_kernel<<<N_TILES, SCAN_TILE, 0, s_side>>>();
    tile_scan_kernel<<<1, 32, 0, s_side>>>();
    tile_write_kernel<<<N_TILES, SCAN_TILE, 0, s_side>>>();
    build_csr_kernel<<<586, 1024, 0, s_side>>>(ei);
    cudaEventRecord(ev_join, s_side);

    int grid = (N_NODES + 127) / 128;
    // input layer: h = relu(x @ W_in + b_in)
    gemm_tf32_kernel<<<grid, 256>>>(x, W_in, b_in, p_h, N_NODES, IN_DIM, 1,
                                    nullptr, nullptr, nullptr, nullptr, nullptr,
                                    nullptr, nullptr, 0);
    // layer 0 conv gemm (plain A = h)
    gemm_tf32_kernel<<<grid, 256>>>(p_h, Wc, nullptr, p_hw, N_NODES, HID, 0,
                                    nullptr, nullptr, nullptr, nullptr, nullptr,
                                    nullptr, nullptr, 0);
    // join: agg needs CSR
    cudaStreamWaitEvent(0, ev_join, 0);
    agg_kernel<<<N_NODES / 8, 256>>>(p_hw, bc, p_t, p_sum, p_sq);

    // layer 1: gemm fused with BN(stats0)+relu (no residual), writes h1
    gemm_tf32_kernel<<<grid, 256>>>(nullptr, Wc + 1 * HID * HID, nullptr, p_hw,
                                    N_NODES, HID, 0,
                                    p_t, p_sum, p_sq, gamma, beta,
                                    nullptr, p_h, 0);
    agg_kernel<<<N_NODES / 8, 256>>>(p_hw, bc + HID, p_t, p_sum + HID, p_sq + HID);

    // layer 2: gemm fused with BN(stats1)+relu+residual(h1), writes h2
    gemm_tf32_kernel<<<grid, 256>>>(nullptr, Wc + 2 * HID * HID, nullptr, p_hw,
                                    N_NODES, HID, 0,
                                    p_t, p_sum + HID, p_sq + HID,
                                    gamma + HID, beta + HID,
                                    p_h, p_h, 1);
    agg_kernel<<<N_NODES / 8, 256>>>(p_hw, bc + 2 * HID, p_t,
                                     p_sum + 2 * HID, p_sq + 2 * HID);

    // output: fused BN(stats2)+relu+residual(h2) then @ W_out + b_out
    out_kernel<<<(N_NODES + 255) / 256, 256>>>(p_t, p_h,
                                               p_sum + 2 * HID, p_sq + 2 * HID,
                                               gamma + 2 * HID, beta + 2 * HID,
                                               W_out, b_out, out);
}

// round 5
// speedup vs baseline: 1.8495x; 1.0849x over previous
#include <cuda_runtime.h>
#include <cuda_fp16.h>
#include <math.h>

#define N_NODES 50000
#define N_EDGES 600000
#define IN_DIM 256
#define HID 128
#define OUT_DIM 10
#define BN_EPS 1e-5f

#define SCAN_TILE 1024
#define N_TILES ((N_NODES + SCAN_TILE - 1) / SCAN_TILE)  // 49

// ---------------- scratch (static __device__ — no allocations) ----------------
__device__ float  g_h[N_NODES * HID];      // activations
__device__ __half g_hwh[N_NODES * HID];    // h @ Wc in fp16 (gather source)
__device__ float  g_t[N_NODES * HID];      // conv output (pre-BN)
__device__ int    g_deg[N_NODES];
__device__ int    g_rowptr[N_NODES + 1];
__device__ int    g_cursor[N_NODES];
__device__ float  g_dinv[N_NODES];
__device__ int    g_csr_src[N_EDGES];
__device__ float  g_csr_w[N_EDGES];        // dinv[src] per edge
__device__ float  g_sum[3 * HID];          // per-layer BN stats
__device__ float  g_sumsq[3 * HID];
__device__ int    g_tilesum[N_TILES];
__device__ int    g_tileoff[N_TILES + 1];
__device__ int    g_is64;

// -------- detect edge dtype (block 0) + zero deg + zero all BN stats ----------
__global__ void detect_zero_kernel(const void* ei) {
    if (blockIdx.x == 0) {
        __shared__ int bad;
        if (threadIdx.x == 0) bad = 0;
        __syncthreads();
        const long long* p = (const long long*)ei;
        for (int i = threadIdx.x; i < 4096; i += blockDim.x) {
            long long v = p[i];
            if (v < 0 || v >= N_NODES) atomicExch(&bad, 1);
        }
        __syncthreads();
        if (threadIdx.x == 0) g_is64 = bad ? 0 : 1;
        if (threadIdx.x < 3 * HID) {
            g_sum[threadIdx.x] = 0.f;
            g_sumsq[threadIdx.x] = 0.f;
        }
    }
    for (int i = blockIdx.x * blockDim.x + threadIdx.x; i < N_NODES;
         i += gridDim.x * blockDim.x)
        g_deg[i] = 0;
}

__device__ __forceinline__ void load_edge(const void* ei, int e, int& s, int& d) {
    if (g_is64) {
        const long long* p = (const long long*)ei;
        s = (int)p[e];
        d = (int)p[N_EDGES + e];
    } else {
        const int* p = (const int*)ei;
        s = p[e];
        d = p[N_EDGES + e];
    }
}

__global__ void count_deg_kernel(const void* ei) {
    for (int e = blockIdx.x * blockDim.x + threadIdx.x; e < N_EDGES;
         e += gridDim.x * blockDim.x) {
        int s, d;
        load_edge(ei, e, s, d);
        atomicAdd(&g_deg[d], 1);
    }
}

// ---- 3-phase coalesced multi-block scan ----
__global__ __launch_bounds__(SCAN_TILE)
void tile_sum_kernel() {
    __shared__ int wsum[32];
    int tid = threadIdx.x, lane = tid & 31, wid = tid >> 5;
    int i = blockIdx.x * SCAN_TILE + tid;
    int d = (i < N_NODES) ? g_deg[i] : 0;
    int v = d;
    #pragma unroll
    for (int off = 16; off > 0; off >>= 1)
        v += __shfl_down_sync(0xffffffffu, v, off);
    if (lane == 0) wsum[wid] = v;
    __syncthreads();
    if (wid == 0) {
        int t2 = wsum[lane];
        #pragma unroll
        for (int off = 16; off > 0; off >>= 1)
            t2 += __shfl_down_sync(0xffffffffu, t2, off);
        if (lane == 0) g_tilesum[blockIdx.x] = t2;
    }
}

__global__ void tile_scan_kernel() {
    int lane = threadIdx.x;
    int run = 0;
    for (int base = 0; base < N_TILES; base += 32) {
        int idx = base + lane;
        int v = (idx < N_TILES) ? g_tilesum[idx] : 0;
        int incl = v;
        #pragma unroll
        for (int off = 1; off < 32; off <<= 1) {
            int t2 = __shfl_up_sync(0xffffffffu, incl, off);
            if (lane >= off) incl += t2;
        }
        if (idx < N_TILES) g_tileoff[idx] = run + incl - v;
        int tot = __shfl_sync(0xffffffffu, incl, 31);
        run += tot;
    }
    if (lane == 0) g_tileoff[N_TILES] = run;
}

__global__ __launch_bounds__(SCAN_TILE)
void tile_write_kernel() {
    __shared__ int wsum[32];
    int tid = threadIdx.x, lane = tid & 31, wid = tid >> 5;
    int i = blockIdx.x * SCAN_TILE + tid;
    int d = (i < N_NODES) ? g_deg[i] : 0;
    int incl = d;
    #pragma unroll
    for (int off = 1; off < 32; off <<= 1) {
        int v = __shfl_up_sync(0xffffffffu, incl, off);
        if (lane >= off) incl += v;
    }
    if (lane == 31) wsum[wid] = incl;
    __syncthreads();
    if (wid == 0) {
        int v = wsum[lane];
        int wi = v;
        #pragma unroll
        for (int off = 1; off < 32; off <<= 1) {
            int t2 = __shfl_up_sync(0xffffffffu, wi, off);
            if (lane >= off) wi += t2;
        }
        wsum[lane] = wi - v;
    }
    __syncthreads();
    int excl = g_tileoff[blockIdx.x] + wsum[wid] + incl - d;
    if (i < N_NODES) {
        g_rowptr[i] = excl;
        g_cursor[i] = excl;
        g_dinv[i]   = rsqrtf((float)d + 1.0f);
    }
    if (i == N_NODES - 1) g_rowptr[N_NODES] = g_tileoff[N_TILES];
}

__global__ void build_csr_kernel(const void* ei) {
    for (int e = blockIdx.x * blockDim.x + threadIdx.x; e < N_EDGES;
         e += gridDim.x * blockDim.x) {
        int s, d;
        load_edge(ei, e, s, d);
        int pos = atomicAdd(&g_cursor[d], 1);
        g_csr_src[pos] = s;
        g_csr_w[pos]   = g_dinv[s];
    }
}

// ---------------- tf32 tensor-core GEMM (optionally fused BN+relu+res on A) ---
__device__ __forceinline__ unsigned f2tf32(float f) {
    unsigned r;
    asm("cvt.rna.tf32.f32 %0, %1;" : "=r"(r) : "f"(f));
    return r;
}

#define APAD 36
#define BPAD 136

// A-side fusion: if t_in != nullptr, A = relu(bn(t_in)) (+hres), written to h_out.
// C-side: if C_half != nullptr, write fp16; else write fp32 C.
__global__ __launch_bounds__(256)
void gemm_tf32_kernel(const float* __restrict__ A_in, const float* __restrict__ W,
                      const float* __restrict__ bias, float* __restrict__ C,
                      __half* __restrict__ C_half,
                      int N, int K, int do_relu,
                      const float* __restrict__ t_in,
                      const float* __restrict__ st_sum, const float* __restrict__ st_sq,
                      const float* __restrict__ gma, const float* __restrict__ bta,
                      const float* __restrict__ hres, float* __restrict__ h_out,
                      int add_res) {
    __shared__ unsigned As[128 * APAD];
    __shared__ unsigned Bs[32 * BPAD];
    __shared__ float s_sc[HID], s_sh[HID];

    int tid = threadIdx.x;
    int w = tid >> 5, lane = tid & 31;
    int wm = (w & 1) * 64;
    int wn = (w >> 1) * 32;
    int gid = lane >> 2, tig = lane & 3;
    int row0 = blockIdx.x * 128;

    if (t_in && tid < HID) {
        float mu  = st_sum[tid] * (1.0f / N_NODES);
        float var = st_sq[tid] * (1.0f / N_NODES) - mu * mu;
        float sc  = gma[tid] * rsqrtf(var + BN_EPS);
        s_sc[tid] = sc;
        s_sh[tid] = bta[tid] - mu * sc;
    }
    __syncthreads();

    float acc[4][4][4];
    #pragma unroll
    for (int i = 0; i < 4; i++)
        #pragma unroll
        for (int j = 0; j < 4; j++)
            #pragma unroll
            for (int c = 0; c < 4; c++) acc[i][j][c] = 0.f;

    for (int k0 = 0; k0 < K; k0 += 32) {
        #pragma unroll
        for (int p = 0; p < 4; p++) {
            int r  = p * 32 + (tid >> 3);
            int kk = (tid & 7) * 4;
            int grow = row0 + r;
            float4 v = make_float4(0.f, 0.f, 0.f, 0.f);
            if (grow < N) {
                size_t off = (size_t)grow * K + k0 + kk;
                if (t_in) {
                    int c = k0 + kk;
                    float4 tv = *(const float4*)&t_in[off];
                    v.x = fmaxf(tv.x * s_sc[c + 0] + s_sh[c + 0], 0.f);
                    v.y = fmaxf(tv.y * s_sc[c + 1] + s_sh[c + 1], 0.f);
                    v.z = fmaxf(tv.z * s_sc[c + 2] + s_sh[c + 2], 0.f);
                    v.w = fmaxf(tv.w * s_sc[c + 3] + s_sh[c + 3], 0.f);
                    if (add_res) {
                        float4 rv = *(const float4*)&hres[off];
                        v.x += rv.x; v.y += rv.y; v.z += rv.z; v.w += rv.w;
                    }
                    *(float4*)&h_out[off] = v;
                } else {
                    v = *(const float4*)&A_in[off];
                }
            }
            unsigned* dst = &As[r * APAD + kk];
            dst[0] = f2tf32(v.x); dst[1] = f2tf32(v.y);
            dst[2] = f2tf32(v.z); dst[3] = f2tf32(v.w);
        }
        #pragma unroll
        for (int p = 0; p < 4; p++) {
            int kk = p * 8 + (tid >> 5);
            int c  = (tid & 31) * 4;
            float4 v = *(const float4*)&W[(size_t)(k0 + kk) * HID + c];
            unsigned* dst = &Bs[kk * BPAD + c];
            dst[0] = f2tf32(v.x); dst[1] = f2tf32(v.y);
            dst[2] = f2tf32(v.z); dst[3] = f2tf32(v.w);
        }
        __syncthreads();

        #pragma unroll
        for (int ks = 0; ks < 4; ks++) {
            int k = ks * 8;
            unsigned afr[4][4], bfr[4][2];
            #pragma unroll
            for (int i = 0; i < 4; i++) {
                int m = wm + i * 16;
                afr[i][0] = As[(m + gid)     * APAD + k + tig];
                afr[i][1] = As[(m + gid + 8) * APAD + k + tig];
                afr[i][2] = As[(m + gid)     * APAD + k + tig + 4];
                afr[i][3] = As[(m + gid + 8) * APAD + k + tig + 4];
            }
            #pragma unroll
            for (int j = 0; j < 4; j++) {
                int n = wn + j * 8 + gid;
                bfr[j][0] = Bs[(k + tig)     * BPAD + n];
                bfr[j][1] = Bs[(k + tig + 4) * BPAD + n];
            }
            #pragma unroll
            for (int i = 0; i < 4; i++)
                #pragma unroll
                for (int j = 0; j < 4; j++) {
                    asm volatile(
                        "mma.sync.aligned.m16n8k8.row.col.f32.tf32.tf32.f32 "
                        "{%0,%1,%2,%3}, {%4,%5,%6,%7}, {%8,%9}, {%0,%1,%2,%3};"
                        : "+f"(acc[i][j][0]), "+f"(acc[i][j][1]),
                          "+f"(acc[i][j][2]), "+f"(acc[i][j][3])
                        : "r"(afr[i][0]), "r"(afr[i][1]),
                          "r"(afr[i][2]), "r"(afr[i][3]),
                          "r"(bfr[j][0]), "r"(bfr[j][1]));
                }
        }
        __syncthreads();
    }

    #pragma unroll
    for (int i = 0; i < 4; i++) {
        int r_up = row0 + wm + i * 16 + gid;
        int r_dn = r_up + 8;
        #pragma unroll
        for (int j = 0; j < 4; j++) {
            int col = wn + j * 8 + 2 * tig;
            float b0 = bias ? bias[col]     : 0.f;
            float b1 = bias ? bias[col + 1] : 0.f;
            float u0 = acc[i][j][0] + b0, u1 = acc[i][j][1] + b1;
            float d0 = acc[i][j][2] + b0, d1 = acc[i][j][3] + b1;
            if (do_relu) {
                u0 = fmaxf(u0, 0.f); u1 = fmaxf(u1, 0.f);
                d0 = fmaxf(d0, 0.f); d1 = fmaxf(d1, 0.f);
            }
            if (C_half) {
                if (r_up < N)
                    *(__half2*)&C_half[(size_t)r_up * HID + col] = __floats2half2_rn(u0, u1);
                if (r_dn < N)
                    *(__half2*)&C_half[(size_t)r_dn * HID + col] = __floats2half2_rn(d0, d1);
            } else {
                if (r_up < N) *(float2*)&C[(size_t)r_up * HID + col] = make_float2(u0, u1);
                if (r_dn < N) *(float2*)&C[(size_t)r_dn * HID + col] = make_float2(d0, d1);
            }
        }
    }
}

// ---------------- aggregation (fp16 gather CSR) + self-loop + bias + BN stats -
__global__ __launch_bounds__(256)
void agg_kernel(const __half* __restrict__ hw, const float* __restrict__ bc,
                float* __restrict__ t, float* __restrict__ st_sum,
                float* __restrict__ st_sq) {
    __shared__ float s_sum[HID], s_sq[HID];
    int tid = threadIdx.x;
    if (tid < HID) { s_sum[tid] = 0.f; s_sq[tid] = 0.f; }
    __syncthreads();

    int lane = tid & 31;
    int n = blockIdx.x * 8 + (tid >> 5);
    if (n < N_NODES) {
        int e0 = g_rowptr[n], e1 = g_rowptr[n + 1];
        float a0 = 0.f, a1 = 0.f, a2 = 0.f, a3 = 0.f;
        int e = e0;
        int s0 = 0, s1 = 0; float w0 = 0.f, w1 = 0.f;
        if (e < e1)     { s0 = __ldg(&g_csr_src[e]);     w0 = __ldg(&g_csr_w[e]); }
        if (e + 1 < e1) { s1 = __ldg(&g_csr_src[e + 1]); w1 = __ldg(&g_csr_w[e + 1]); }
        while (e < e1) {
            int s = s0; float w = w0;
            s0 = s1; w0 = w1;
            if (e + 2 < e1) { s1 = __ldg(&g_csr_src[e + 2]); w1 = __ldg(&g_csr_w[e + 2]); }
            // lane covers cols [lane*4, lane*4+4): 8 bytes of fp16
            uint2 u = __ldg((const uint2*)(hw + (size_t)s * HID) + lane);
            float2 f0 = __half22float2(*(const __half2*)&u.x);
            float2 f1 = __half22float2(*(const __half2*)&u.y);
            a0 += f0.x * w; a1 += f0.y * w; a2 += f1.x * w; a3 += f1.y * w;
            e++;
        }
        float di  = g_dinv[n];
        float dii = di * di;
        int c = lane * 4;
        uint2 su = __ldg((const uint2*)(hw + (size_t)n * HID) + lane);
        float2 sf0 = __half22float2(*(const __half2*)&su.x);
        float2 sf1 = __half22float2(*(const __half2*)&su.y);
        float t0 = a0 * di + sf0.x * dii + bc[c + 0];
        float t1 = a1 * di + sf0.y * dii + bc[c + 1];
        float t2 = a2 * di + sf1.x * dii + bc[c + 2];
        float t3 = a3 * di + sf1.y * dii + bc[c + 3];
        *(float4*)(t + (size_t)n * HID + c) = make_float4(t0, t1, t2, t3);
        atomicAdd(&s_sum[c + 0], t0); atomicAdd(&s_sq[c + 0], t0 * t0);
        atomicAdd(&s_sum[c + 1], t1); atomicAdd(&s_sq[c + 1], t1 * t1);
        atomicAdd(&s_sum[c + 2], t2); atomicAdd(&s_sq[c + 2], t2 * t2);
        atomicAdd(&s_sum[c + 3], t3); atomicAdd(&s_sq[c + 3], t3 * t3);
    }
    __syncthreads();
    if (tid < HID) {
        atomicAdd(&st_sum[tid], s_sum[tid]);
        atomicAdd(&st_sq[tid],  s_sq[tid]);
    }
}

// ------- output projection fused with final BN+relu+residual ------------------
__global__ __launch_bounds__(256)
void out_kernel(const float* __restrict__ t, const float* __restrict__ hres,
                const float* __restrict__ st_sum, const float* __restrict__ st_sq,
                const float* __restrict__ gma, const float* __restrict__ bta,
                const float* __restrict__ Wo, const float* __restrict__ bo,
                float* __restrict__ out) {
    __shared__ float ws[HID * OUT_DIM];
    __shared__ float bs[OUT_DIM];
    __shared__ float s_sc[HID], s_sh[HID];
    int tid = threadIdx.x;
    for (int i = tid; i < HID * OUT_DIM; i += blockDim.x) ws[i] = Wo[i];
    if (tid < OUT_DIM) bs[tid] = bo[tid];
    if (tid < HID) {
        float mu  = st_sum[tid] * (1.0f / N_NODES);
        float var = st_sq[tid] * (1.0f / N_NODES) - mu * mu;
        float sc  = gma[tid] * rsqrtf(var + BN_EPS);
        s_sc[tid] = sc;
        s_sh[tid] = bta[tid] - mu * sc;
    }
    __syncthreads();
    int n = blockIdx.x * blockDim.x + tid;
    if (n >= N_NODES) return;
    float acc[OUT_DIM];
    #pragma unroll
    for (int o = 0; o < OUT_DIM; o++) acc[o] = bs[o];
    const float4* tp = (const float4*)(t + (size_t)n * HID);
    const float4* rp = (const float4*)(hres + (size_t)n * HID);
    #pragma unroll 4
    for (int k4 = 0; k4 < HID / 4; k4++) {
        float4 tv = tp[k4];
        float4 rv = rp[k4];
        int kb = k4 * 4;
        float a0 = fmaxf(tv.x * s_sc[kb + 0] + s_sh[kb + 0], 0.f) + rv.x;
        float a1 = fmaxf(tv.y * s_sc[kb + 1] + s_sh[kb + 1], 0.f) + rv.y;
        float a2 = fmaxf(tv.z * s_sc[kb + 2] + s_sh[kb + 2], 0.f) + rv.z;
        float a3 = fmaxf(tv.w * s_sc[kb + 3] + s_sh[kb + 3], 0.f) + rv.w;
        #pragma unroll
        for (int o = 0; o < OUT_DIM; o++) {
            acc[o] += a0 * ws[(kb + 0) * OUT_DIM + o]
                    + a1 * ws[(kb + 1) * OUT_DIM + o]
                    + a2 * ws[(kb + 2) * OUT_DIM + o]
                    + a3 * ws[(kb + 3) * OUT_DIM + o];
        }
    }
    #pragma unroll
    for (int o = 0; o < OUT_DIM; o++) out[n * OUT_DIM + o] = acc[o];
}

// ---------------- launch ----------------
extern "C" void kernel_launch(void* const* d_in, const int* in_sizes, int n_in,
                              void* d_out, int out_size) {
    const float* x     = (const float*)d_in[0];
    const void*  ei    = d_in[1];
    const float* W_in  = (const float*)d_in[2];
    const float* b_in  = (const float*)d_in[3];
    const float* Wc    = (const float*)d_in[4];
    const float* bc    = (const float*)d_in[5];
    const float* gamma = (const float*)d_in[6];
    const float* beta  = (const float*)d_in[7];
    const float* W_out = (const float*)d_in[8];
    const float* b_out = (const float*)d_in[9];
    float* out = (float*)d_out;

    float *p_h, *p_t, *p_sum, *p_sq;
    __half* p_hwh;
    cudaGetSymbolAddress((void**)&p_h,   g_h);
    cudaGetSymbolAddress((void**)&p_hwh, g_hwh);
    cudaGetSymbolAddress((void**)&p_t,   g_t);
    cudaGetSymbolAddress((void**)&p_sum, g_sum);
    cudaGetSymbolAddress((void**)&p_sq,  g_sumsq);

    static cudaStream_t s_side = nullptr;
    static cudaEvent_t ev_fork = nullptr, ev_join = nullptr;
    if (!s_side) {
        cudaStreamCreateWithFlags(&s_side, cudaStreamNonBlocking);
        cudaEventCreateWithFlags(&ev_fork, cudaEventDisableTiming);
        cudaEventCreateWithFlags(&ev_join, cudaEventDisableTiming);
    }

    // fork: CSR build on side stream, overlapped with input + layer-0 GEMMs
    cudaEventRecord(ev_fork, 0);
    cudaStreamWaitEvent(s_side, ev_fork, 0);
    detect_zero_kernel<<<99, 512, 0, s_side>>>(ei);
    count_deg_kernel<<<586, 1024, 0, s_side>>>(ei);
    tile_sum_kernel<<<N_TILES, SCAN_TILE, 0, s_side>>>();
    tile_scan_kernel<<<1, 32, 0, s_side>>>();
    tile_write_kernel<<<N_TILES, SCAN_TILE, 0, s_side>>>();
    build_csr_kernel<<<586, 1024, 0, s_side>>>(ei);
    cudaEventRecord(ev_join, s_side);

    int grid = (N_NODES + 127) / 128;
    // input layer: h = relu(x @ W_in + b_in), fp32 out
    gemm_tf32_kernel<<<grid, 256>>>(x, W_in, b_in, p_h, nullptr,
                                    N_NODES, IN_DIM, 1,
                                    nullptr, nullptr, nullptr, nullptr, nullptr,
                                    nullptr, nullptr, 0);
    // layer 0 conv gemm: hw (fp16) = h @ Wc0
    gemm_tf32_kernel<<<grid, 256>>>(p_h, Wc, nullptr, nullptr, p_hwh,
                                    N_NODES, HID, 0,
                                    nullptr, nullptr, nullptr, nullptr, nullptr,
                                    nullptr, nullptr, 0);
    // join: agg needs CSR
    cudaStreamWaitEvent(0, ev_join, 0);
    agg_kernel<<<N_NODES / 8, 256>>>(p_hwh, bc, p_t, p_sum, p_sq);

    // layer 1: gemm fused with BN(stats0)+relu, writes h1 (fp32) and hw (fp16)
    gemm_tf32_kernel<<<grid, 256>>>(nullptr, Wc + 1 * HID * HID, nullptr,
                                    nullptr, p_hwh,
                                    N_NODES, HID, 0,
                                    p_t, p_sum, p_sq, gamma, beta,
                                    nullptr, p_h, 0);
    agg_kernel<<<N_NODES / 8, 256>>>(p_hwh, bc + HID, p_t, p_sum + HID, p_sq + HID);

    // layer 2: gemm fused with BN(stats1)+relu+residual(h1), writes h2, hw fp16
    gemm_tf32_kernel<<<grid, 256>>>(nullptr, Wc + 2 * HID * HID, nullptr,
                                    nullptr, p_hwh,
                                    N_NODES, HID, 0,
                                    p_t, p_sum + HID, p_sq + HID,
                                    gamma + HID, beta + HID,
                                    p_h, p_h, 1);
    agg_kernel<<<N_NODES / 8, 256>>>(p_hwh, bc + 2 * HID, p_t,
                                     p_sum + 2 * HID, p_sq + 2 * HID);

    // output: fused BN(stats2)+relu+residual(h2) then @ W_out + b_out
    out_kernel<<<(N_NODES + 255) / 256, 256>>>(p_t, p_h,
                                               p_sum + 2 * HID, p_sq + 2 * HID,
                                               gamma + 2 * HID, beta + 2 * HID,
                                               W_out, b_out, out);
}

// round 6
// speedup vs baseline: 1.9282x; 1.0425x over previous
#include <cuda_runtime.h>
#include <cuda_fp16.h>
#include <math.h>

#define N_NODES 50000
#define N_EDGES 600000
#define IN_DIM 256
#define HID 128
#define OUT_DIM 10
#define BN_EPS 1e-5f

#define SCAN_TILE 1024
#define N_TILES ((N_NODES + SCAN_TILE - 1) / SCAN_TILE)  // 49

// ---------------- scratch (static __device__ — no allocations) ----------------
__device__ float  g_h[N_NODES * HID];      // activations
__device__ __half g_hwh[N_NODES * HID];    // h @ Wc in fp16 (gather source)
__device__ float  g_t[N_NODES * HID];      // conv output (pre-BN)
__device__ int    g_deg[N_NODES];
__device__ int    g_rowptr[N_NODES + 1];
__device__ int    g_cursor[N_NODES];
__device__ float  g_dinv[N_NODES];
__device__ int    g_csr_src[N_EDGES];
__device__ float  g_csr_w[N_EDGES];        // dinv[src] per edge
__device__ float  g_sum[3 * HID];          // per-layer BN stats
__device__ float  g_sumsq[3 * HID];
__device__ int    g_tilesum[N_TILES];
__device__ int    g_tileoff[N_TILES + 1];
__device__ int    g_is64;

// -------- detect edge dtype (block 0) + zero deg + zero all BN stats ----------
__global__ void detect_zero_kernel(const void* ei) {
    if (blockIdx.x == 0) {
        __shared__ int bad;
        if (threadIdx.x == 0) bad = 0;
        __syncthreads();
        const long long* p = (const long long*)ei;
        for (int i = threadIdx.x; i < 4096; i += blockDim.x) {
            long long v = p[i];
            if (v < 0 || v >= N_NODES) atomicExch(&bad, 1);
        }
        __syncthreads();
        if (threadIdx.x == 0) g_is64 = bad ? 0 : 1;
        if (threadIdx.x < 3 * HID) {
            g_sum[threadIdx.x] = 0.f;
            g_sumsq[threadIdx.x] = 0.f;
        }
    }
    for (int i = blockIdx.x * blockDim.x + threadIdx.x; i < N_NODES;
         i += gridDim.x * blockDim.x)
        g_deg[i] = 0;
}

__device__ __forceinline__ void load_edge(const void* ei, int e, int& s, int& d) {
    if (g_is64) {
        const long long* p = (const long long*)ei;
        s = (int)p[e];
        d = (int)p[N_EDGES + e];
    } else {
        const int* p = (const int*)ei;
        s = p[e];
        d = p[N_EDGES + e];
    }
}

__global__ void count_deg_kernel(const void* ei) {
    for (int e = blockIdx.x * blockDim.x + threadIdx.x; e < N_EDGES;
         e += gridDim.x * blockDim.x) {
        int s, d;
        load_edge(ei, e, s, d);
        atomicAdd(&g_deg[d], 1);
    }
}

// ---- 3-phase coalesced multi-block scan ----
__global__ __launch_bounds__(SCAN_TILE)
void tile_sum_kernel() {
    __shared__ int wsum[32];
    int tid = threadIdx.x, lane = tid & 31, wid = tid >> 5;
    int i = blockIdx.x * SCAN_TILE + tid;
    int d = (i < N_NODES) ? g_deg[i] : 0;
    int v = d;
    #pragma unroll
    for (int off = 16; off > 0; off >>= 1)
        v += __shfl_down_sync(0xffffffffu, v, off);
    if (lane == 0) wsum[wid] = v;
    __syncthreads();
    if (wid == 0) {
        int t2 = wsum[lane];
        #pragma unroll
        for (int off = 16; off > 0; off >>= 1)
            t2 += __shfl_down_sync(0xffffffffu, t2, off);
        if (lane == 0) g_tilesum[blockIdx.x] = t2;
    }
}

__global__ void tile_scan_kernel() {
    int lane = threadIdx.x;
    int run = 0;
    for (int base = 0; base < N_TILES; base += 32) {
        int idx = base + lane;
        int v = (idx < N_TILES) ? g_tilesum[idx] : 0;
        int incl = v;
        #pragma unroll
        for (int off = 1; off < 32; off <<= 1) {
            int t2 = __shfl_up_sync(0xffffffffu, incl, off);
            if (lane >= off) incl += t2;
        }
        if (idx < N_TILES) g_tileoff[idx] = run + incl - v;
        int tot = __shfl_sync(0xffffffffu, incl, 31);
        run += tot;
    }
    if (lane == 0) g_tileoff[N_TILES] = run;
}

__global__ __launch_bounds__(SCAN_TILE)
void tile_write_kernel() {
    __shared__ int wsum[32];
    int tid = threadIdx.x, lane = tid & 31, wid = tid >> 5;
    int i = blockIdx.x * SCAN_TILE + tid;
    int d = (i < N_NODES) ? g_deg[i] : 0;
    int incl = d;
    #pragma unroll
    for (int off = 1; off < 32; off <<= 1) {
        int v = __shfl_up_sync(0xffffffffu, incl, off);
        if (lane >= off) incl += v;
    }
    if (lane == 31) wsum[wid] = incl;
    __syncthreads();
    if (wid == 0) {
        int v = wsum[lane];
        int wi = v;
        #pragma unroll
        for (int off = 1; off < 32; off <<= 1) {
            int t2 = __shfl_up_sync(0xffffffffu, wi, off);
            if (lane >= off) wi += t2;
        }
        wsum[lane] = wi - v;
    }
    __syncthreads();
    int excl = g_tileoff[blockIdx.x] + wsum[wid] + incl - d;
    if (i < N_NODES) {
        g_rowptr[i] = excl;
        g_cursor[i] = excl;
        g_dinv[i]   = rsqrtf((float)d + 1.0f);
    }
    if (i == N_NODES - 1) g_rowptr[N_NODES] = g_tileoff[N_TILES];
}

__global__ void build_csr_kernel(const void* ei) {
    for (int e = blockIdx.x * blockDim.x + threadIdx.x; e < N_EDGES;
         e += gridDim.x * blockDim.x) {
        int s, d;
        load_edge(ei, e, s, d);
        int pos = atomicAdd(&g_cursor[d], 1);
        g_csr_src[pos] = s;
        g_csr_w[pos]   = g_dinv[s];
    }
}

// ---------------- fp16 tensor-core GEMM (m16n8k16, fp32 accumulate) ----------
// block tile 128x128, 8 warps, warp tile 64x32.
// As: half2 [m][k2], stride 20 (4B units) — fragment banks gid*20+tig all distinct
// Bs: half2 [k2][n], stride 136 — k-adjacent pair packed in half2 (B fragment)

#define SA 20
#define SB 136

__global__ __launch_bounds__(256)
void gemm_fp16_kernel(const float* __restrict__ A_in, const float* __restrict__ W,
                      const float* __restrict__ bias, float* __restrict__ C,
                      __half* __restrict__ C_half,
                      int N, int K, int do_relu,
                      const float* __restrict__ t_in,
                      const float* __restrict__ st_sum, const float* __restrict__ st_sq,
                      const float* __restrict__ gma, const float* __restrict__ bta,
                      const float* __restrict__ hres, float* __restrict__ h_out,
                      int add_res) {
    __shared__ unsigned As[128 * SA];   // half2 bits
    __shared__ unsigned Bs[16 * SB];    // half2 bits
    __shared__ float s_sc[HID], s_sh[HID];

    int tid = threadIdx.x;
    int w = tid >> 5, lane = tid & 31;
    int wm = (w & 1) * 64;
    int wn = (w >> 1) * 32;
    int gid = lane >> 2, tig = lane & 3;
    int row0 = blockIdx.x * 128;

    if (t_in && tid < HID) {
        float mu  = st_sum[tid] * (1.0f / N_NODES);
        float var = st_sq[tid] * (1.0f / N_NODES) - mu * mu;
        float sc  = gma[tid] * rsqrtf(var + BN_EPS);
        s_sc[tid] = sc;
        s_sh[tid] = bta[tid] - mu * sc;
    }
    __syncthreads();

    float acc[4][4][4];
    #pragma unroll
    for (int i = 0; i < 4; i++)
        #pragma unroll
        for (int j = 0; j < 4; j++)
            #pragma unroll
            for (int c = 0; c < 4; c++) acc[i][j][c] = 0.f;

    for (int k0 = 0; k0 < K; k0 += 32) {
        // ---- stage A tile 128x32 fp32 -> half2 ----
        #pragma unroll
        for (int p = 0; p < 4; p++) {
            int r   = p * 32 + (tid >> 3);
            int kk  = (tid & 7) * 4;        // fp32 k offset
            int grow = row0 + r;
            float4 v = make_float4(0.f, 0.f, 0.f, 0.f);
            if (grow < N) {
                size_t off = (size_t)grow * K + k0 + kk;
                if (t_in) {
                    int c = k0 + kk;
                    float4 tv = *(const float4*)&t_in[off];
                    v.x = fmaxf(tv.x * s_sc[c + 0] + s_sh[c + 0], 0.f);
                    v.y = fmaxf(tv.y * s_sc[c + 1] + s_sh[c + 1], 0.f);
                    v.z = fmaxf(tv.z * s_sc[c + 2] + s_sh[c + 2], 0.f);
                    v.w = fmaxf(tv.w * s_sc[c + 3] + s_sh[c + 3], 0.f);
                    if (add_res) {
                        float4 rv = *(const float4*)&hres[off];
                        v.x += rv.x; v.y += rv.y; v.z += rv.z; v.w += rv.w;
                    }
                    *(float4*)&h_out[off] = v;
                } else {
                    v = *(const float4*)&A_in[off];
                }
            }
            __half2 h0 = __floats2half2_rn(v.x, v.y);
            __half2 h1 = __floats2half2_rn(v.z, v.w);
            uint2 u = make_uint2(*(unsigned*)&h0, *(unsigned*)&h1);
            *(uint2*)&As[r * SA + (kk >> 1)] = u;   // 8B aligned (kk>>1 even)
        }
        // ---- stage W tile 32x128 fp32 -> half2 (k-pair packed) ----
        #pragma unroll
        for (int p = 0; p < 2; p++) {
            int k2 = p * 8 + (tid >> 5);    // 0..15
            int c  = (tid & 31) * 4;
            const float* wlo = &W[(size_t)(k0 + 2 * k2)     * HID + c];
            const float* whi = &W[(size_t)(k0 + 2 * k2 + 1) * HID + c];
            float4 lo = *(const float4*)wlo;
            float4 hi = *(const float4*)whi;
            __half2 q0 = __floats2half2_rn(lo.x, hi.x);
            __half2 q1 = __floats2half2_rn(lo.y, hi.y);
            __half2 q2 = __floats2half2_rn(lo.z, hi.z);
            __half2 q3 = __floats2half2_rn(lo.w, hi.w);
            uint4 u = make_uint4(*(unsigned*)&q0, *(unsigned*)&q1,
                                 *(unsigned*)&q2, *(unsigned*)&q3);
            *(uint4*)&Bs[k2 * SB + c] = u;  // 16B aligned (544*k2 + 16*(c/4))
        }
        __syncthreads();

        #pragma unroll
        for (int s = 0; s < 2; s++) {       // two k16-steps per 32-K
            int base = s * 8;               // k2 base
            unsigned afr[4][4], bfr[4][2];
            #pragma unroll
            for (int i = 0; i < 4; i++) {
                int m = wm + i * 16;
                afr[i][0] = As[(m + gid)     * SA + base + tig];
                afr[i][1] = As[(m + gid + 8) * SA + base + tig];
                afr[i][2] = As[(m + gid)     * SA + base + tig + 4];
                afr[i][3] = As[(m + gid + 8) * SA + base + tig + 4];
            }
            #pragma unroll
            for (int j = 0; j < 4; j++) {
                int n = wn + j * 8 + gid;
                bfr[j][0] = Bs[(base + tig)     * SB + n];
                bfr[j][1] = Bs[(base + tig + 4) * SB + n];
            }
            #pragma unroll
            for (int i = 0; i < 4; i++)
                #pragma unroll
                for (int j = 0; j < 4; j++) {
                    asm volatile(
                        "mma.sync.aligned.m16n8k16.row.col.f32.f16.f16.f32 "
                        "{%0,%1,%2,%3}, {%4,%5,%6,%7}, {%8,%9}, {%0,%1,%2,%3};"
                        : "+f"(acc[i][j][0]), "+f"(acc[i][j][1]),
                          "+f"(acc[i][j][2]), "+f"(acc[i][j][3])
                        : "r"(afr[i][0]), "r"(afr[i][1]),
                          "r"(afr[i][2]), "r"(afr[i][3]),
                          "r"(bfr[j][0]), "r"(bfr[j][1]));
                }
        }
        __syncthreads();
    }

    #pragma unroll
    for (int i = 0; i < 4; i++) {
        int r_up = row0 + wm + i * 16 + gid;
        int r_dn = r_up + 8;
        #pragma unroll
        for (int j = 0; j < 4; j++) {
            int col = wn + j * 8 + 2 * tig;
            float b0 = bias ? bias[col]     : 0.f;
            float b1 = bias ? bias[col + 1] : 0.f;
            float u0 = acc[i][j][0] + b0, u1 = acc[i][j][1] + b1;
            float d0 = acc[i][j][2] + b0, d1 = acc[i][j][3] + b1;
            if (do_relu) {
                u0 = fmaxf(u0, 0.f); u1 = fmaxf(u1, 0.f);
                d0 = fmaxf(d0, 0.f); d1 = fmaxf(d1, 0.f);
            }
            if (C_half) {
                if (r_up < N)
                    *(__half2*)&C_half[(size_t)r_up * HID + col] = __floats2half2_rn(u0, u1);
                if (r_dn < N)
                    *(__half2*)&C_half[(size_t)r_dn * HID + col] = __floats2half2_rn(d0, d1);
            } else {
                if (r_up < N) *(float2*)&C[(size_t)r_up * HID + col] = make_float2(u0, u1);
                if (r_dn < N) *(float2*)&C[(size_t)r_dn * HID + col] = make_float2(d0, d1);
            }
        }
    }
}

// ---------------- aggregation (fp16 gather CSR) + self-loop + bias + BN stats -
__global__ __launch_bounds__(256)
void agg_kernel(const __half* __restrict__ hw, const float* __restrict__ bc,
                float* __restrict__ t, float* __restrict__ st_sum,
                float* __restrict__ st_sq) {
    __shared__ float s_sum[HID], s_sq[HID];
    int tid = threadIdx.x;
    if (tid < HID) { s_sum[tid] = 0.f; s_sq[tid] = 0.f; }
    __syncthreads();

    int lane = tid & 31;
    int n = blockIdx.x * 8 + (tid >> 5);
    if (n < N_NODES) {
        int e0 = g_rowptr[n], e1 = g_rowptr[n + 1];
        float a0 = 0.f, a1 = 0.f, a2 = 0.f, a3 = 0.f;
        int e = e0;
        int s0 = 0, s1 = 0; float w0 = 0.f, w1 = 0.f;
        if (e < e1)     { s0 = __ldg(&g_csr_src[e]);     w0 = __ldg(&g_csr_w[e]); }
        if (e + 1 < e1) { s1 = __ldg(&g_csr_src[e + 1]); w1 = __ldg(&g_csr_w[e + 1]); }
        while (e < e1) {
            int s = s0; float w = w0;
            s0 = s1; w0 = w1;
            if (e + 2 < e1) { s1 = __ldg(&g_csr_src[e + 2]); w1 = __ldg(&g_csr_w[e + 2]); }
            uint2 u = __ldg((const uint2*)(hw + (size_t)s * HID) + lane);
            float2 f0 = __half22float2(*(const __half2*)&u.x);
            float2 f1 = __half22float2(*(const __half2*)&u.y);
            a0 += f0.x * w; a1 += f0.y * w; a2 += f1.x * w; a3 += f1.y * w;
            e++;
        }
        float di  = g_dinv[n];
        float dii = di * di;
        int c = lane * 4;
        uint2 su = __ldg((const uint2*)(hw + (size_t)n * HID) + lane);
        float2 sf0 = __half22float2(*(const __half2*)&su.x);
        float2 sf1 = __half22float2(*(const __half2*)&su.y);
        float t0 = a0 * di + sf0.x * dii + bc[c + 0];
        float t1 = a1 * di + sf0.y * dii + bc[c + 1];
        float t2 = a2 * di + sf1.x * dii + bc[c + 2];
        float t3 = a3 * di + sf1.y * dii + bc[c + 3];
        *(float4*)(t + (size_t)n * HID + c) = make_float4(t0, t1, t2, t3);
        atomicAdd(&s_sum[c + 0], t0); atomicAdd(&s_sq[c + 0], t0 * t0);
        atomicAdd(&s_sum[c + 1], t1); atomicAdd(&s_sq[c + 1], t1 * t1);
        atomicAdd(&s_sum[c + 2], t2); atomicAdd(&s_sq[c + 2], t2 * t2);
        atomicAdd(&s_sum[c + 3], t3); atomicAdd(&s_sq[c + 3], t3 * t3);
    }
    __syncthreads();
    if (tid < HID) {
        atomicAdd(&st_sum[tid], s_sum[tid]);
        atomicAdd(&st_sq[tid],  s_sq[tid]);
    }
}

// ------- output projection fused with final BN+relu+residual ------------------
__global__ __launch_bounds__(256)
void out_kernel(const float* __restrict__ t, const float* __restrict__ hres,
                const float* __restrict__ st_sum, const float* __restrict__ st_sq,
                const float* __restrict__ gma, const float* __restrict__ bta,
                const float* __restrict__ Wo, const float* __restrict__ bo,
                float* __restrict__ out) {
    __shared__ float ws[HID * OUT_DIM];
    __shared__ float bs[OUT_DIM];
    __shared__ float s_sc[HID], s_sh[HID];
    int tid = threadIdx.x;
    for (int i = tid; i < HID * OUT_DIM; i += blockDim.x) ws[i] = Wo[i];
    if (tid < OUT_DIM) bs[tid] = bo[tid];
    if (tid < HID) {
        float mu  = st_sum[tid] * (1.0f / N_NODES);
        float var = st_sq[tid] * (1.0f / N_NODES) - mu * mu;
        float sc  = gma[tid] * rsqrtf(var + BN_EPS);
        s_sc[tid] = sc;
        s_sh[tid] = bta[tid] - mu * sc;
    }
    __syncthreads();
    int n = blockIdx.x * blockDim.x + tid;
    if (n >= N_NODES) return;
    float acc[OUT_DIM];
    #pragma unroll
    for (int o = 0; o < OUT_DIM; o++) acc[o] = bs[o];
    const float4* tp = (const float4*)(t + (size_t)n * HID);
    const float4* rp = (const float4*)(hres + (size_t)n * HID);
    #pragma unroll 4
    for (int k4 = 0; k4 < HID / 4; k4++) {
        float4 tv = tp[k4];
        float4 rv = rp[k4];
        int kb = k4 * 4;
        float a0 = fmaxf(tv.x * s_sc[kb + 0] + s_sh[kb + 0], 0.f) + rv.x;
        float a1 = fmaxf(tv.y * s_sc[kb + 1] + s_sh[kb + 1], 0.f) + rv.y;
        float a2 = fmaxf(tv.z * s_sc[kb + 2] + s_sh[kb + 2], 0.f) + rv.z;
        float a3 = fmaxf(tv.w * s_sc[kb + 3] + s_sh[kb + 3], 0.f) + rv.w;
        #pragma unroll
        for (int o = 0; o < OUT_DIM; o++) {
            acc[o] += a0 * ws[(kb + 0) * OUT_DIM + o]
                    + a1 * ws[(kb + 1) * OUT_DIM + o]
                    + a2 * ws[(kb + 2) * OUT_DIM + o]
                    + a3 * ws[(kb + 3) * OUT_DIM + o];
        }
    }
    #pragma unroll
    for (int o = 0; o < OUT_DIM; o++) out[n * OUT_DIM + o] = acc[o];
}

// ---------------- launch ----------------
extern "C" void kernel_launch(void* const* d_in, const int* in_sizes, int n_in,
                              void* d_out, int out_size) {
    const float* x     = (const float*)d_in[0];
    const void*  ei    = d_in[1];
    const float* W_in  = (const float*)d_in[2];
    const float* b_in  = (const float*)d_in[3];
    const float* Wc    = (const float*)d_in[4];
    const float* bc    = (const float*)d_in[5];
    const float* gamma = (const float*)d_in[6];
    const float* beta  = (const float*)d_in[7];
    const float* W_out = (const float*)d_in[8];
    const float* b_out = (const float*)d_in[9];
    float* out = (float*)d_out;

    float *p_h, *p_t, *p_sum, *p_sq;
    __half* p_hwh;
    cudaGetSymbolAddress((void**)&p_h,   g_h);
    cudaGetSymbolAddress((void**)&p_hwh, g_hwh);
    cudaGetSymbolAddress((void**)&p_t,   g_t);
    cudaGetSymbolAddress((void**)&p_sum, g_sum);
    cudaGetSymbolAddress((void**)&p_sq,  g_sumsq);

    static cudaStream_t s_side = nullptr;
    static cudaEvent_t ev_fork = nullptr, ev_join = nullptr;
    if (!s_side) {
        cudaStreamCreateWithFlags(&s_side, cudaStreamNonBlocking);
        cudaEventCreateWithFlags(&ev_fork, cudaEventDisableTiming);
        cudaEventCreateWithFlags(&ev_join, cudaEventDisableTiming);
    }

    // fork: CSR build on side stream, overlapped with input + layer-0 GEMMs
    cudaEventRecord(ev_fork, 0);
    cudaStreamWaitEvent(s_side, ev_fork, 0);
    detect_zero_kernel<<<99, 512, 0, s_side>>>(ei);
    count_deg_kernel<<<586, 1024, 0, s_side>>>(ei);
    tile_sum_kernel<<<N_TILES, SCAN_TILE, 0, s_side>>>();
    tile_scan_kernel<<<1, 32, 0, s_side>>>();
    tile_write_kernel<<<N_TILES, SCAN_TILE, 0, s_side>>>();
    build_csr_kernel<<<586, 1024, 0, s_side>>>(ei);
    cudaEventRecord(ev_join, s_side);

    int grid = (N_NODES + 127) / 128;
    // input layer: h = relu(x @ W_in + b_in), fp32 out
    gemm_fp16_kernel<<<grid, 256>>>(x, W_in, b_in, p_h, nullptr,
                                    N_NODES, IN_DIM, 1,
                                    nullptr, nullptr, nullptr, nullptr, nullptr,
                                    nullptr, nullptr, 0);
    // layer 0 conv gemm: hw (fp16) = h @ Wc0
    gemm_fp16_kernel<<<grid, 256>>>(p_h, Wc, nullptr, nullptr, p_hwh,
                                    N_NODES, HID, 0,
                                    nullptr, nullptr, nullptr, nullptr, nullptr,
                                    nullptr, nullptr, 0);
    // join: agg needs CSR
    cudaStreamWaitEvent(0, ev_join, 0);
    agg_kernel<<<N_NODES / 8, 256>>>(p_hwh, bc, p_t, p_sum, p_sq);

    // layer 1: gemm fused with BN(stats0)+relu, writes h1 (fp32) and hw (fp16)
    gemm_fp16_kernel<<<grid, 256>>>(nullptr, Wc + 1 * HID * HID, nullptr,
                                    nullptr, p_hwh,
                                    N_NODES, HID, 0,
                                    p_t, p_sum, p_sq, gamma, beta,
                                    nullptr, p_h, 0);
    agg_kernel<<<N_NODES / 8, 256>>>(p_hwh, bc + HID, p_t, p_sum + HID, p_sq + HID);

    // layer 2: gemm fused with BN(stats1)+relu+residual(h1), writes h2, hw fp16
    gemm_fp16_kernel<<<grid, 256>>>(nullptr, Wc + 2 * HID * HID, nullptr,
                                    nullptr, p_hwh,
                                    N_NODES, HID, 0,
                                    p_t, p_sum + HID, p_sq + HID,
                                    gamma + HID, beta + HID,
                                    p_h, p_h, 1);
    agg_kernel<<<N_NODES / 8, 256>>>(p_hwh, bc + 2 * HID, p_t,
                                     p_sum + 2 * HID, p_sq + 2 * HID);

    // output: fused BN(stats2)+relu+residual(h2) then @ W_out + b_out
    out_kernel<<<(N_NODES + 255) / 256, 256>>>(p_t, p_h,
                                               p_sum + 2 * HID, p_sq + 2 * HID,
                                               gamma + 2 * HID, beta + 2 * HID,
                                               W_out, b_out, out);
}

// round 7
// speedup vs baseline: 2.0821x; 1.0798x over previous
#include <cuda_runtime.h>
#include <cuda_fp16.h>
#include <math.h>

#define N_NODES 50000
#define N_EDGES 600000
#define IN_DIM 256
#define HID 128
#define OUT_DIM 10
#define BN_EPS 1e-5f

#define SCAN_TILE 1024
#define N_TILES ((N_NODES + SCAN_TILE - 1) / SCAN_TILE)  // 49

// ---------------- scratch (static __device__ — no allocations) ----------------
__device__ float  g_h[N_NODES * HID];
__device__ __half g_hwh[N_NODES * HID];
__device__ float  g_t[N_NODES * HID];
__device__ int    g_deg[N_NODES];
__device__ int    g_rowptr[N_NODES + 1];
__device__ int    g_cursor[N_NODES];
__device__ float  g_dinv[N_NODES];
__device__ unsigned long long g_csr[N_EDGES];   // packed (w<<32 | src)
__device__ float  g_sum[3 * HID];
__device__ float  g_sumsq[3 * HID];
__device__ int    g_tilesum[N_TILES];
__device__ int    g_tileoff[N_TILES + 1];
__device__ int    g_ticket;
__device__ int    g_is64;

// -------- detect edge dtype + zero deg + zero BN stats + ticket --------------
__global__ void detect_zero_kernel(const void* ei) {
    if (blockIdx.x == 0) {
        __shared__ int bad;
        if (threadIdx.x == 0) bad = 0;
        __syncthreads();
        const long long* p = (const long long*)ei;
        for (int i = threadIdx.x; i < 4096; i += blockDim.x) {
            long long v = p[i];
            if (v < 0 || v >= N_NODES) atomicExch(&bad, 1);
        }
        __syncthreads();
        if (threadIdx.x == 0) { g_is64 = bad ? 0 : 1; g_ticket = 0; }
        if (threadIdx.x < 3 * HID) {
            g_sum[threadIdx.x] = 0.f;
            g_sumsq[threadIdx.x] = 0.f;
        }
    }
    for (int i = blockIdx.x * blockDim.x + threadIdx.x; i < N_NODES;
         i += gridDim.x * blockDim.x)
        g_deg[i] = 0;
}

__device__ __forceinline__ void load_edge(const void* ei, int e, int& s, int& d) {
    if (g_is64) {
        const long long* p = (const long long*)ei;
        s = (int)p[e];
        d = (int)p[N_EDGES + e];
    } else {
        const int* p = (const int*)ei;
        s = p[e];
        d = p[N_EDGES + e];
    }
}

// count: reads dst half only
__global__ void count_deg_kernel(const void* ei) {
    for (int e = blockIdx.x * blockDim.x + threadIdx.x; e < N_EDGES;
         e += gridDim.x * blockDim.x) {
        int d;
        if (g_is64) d = (int)((const long long*)ei)[N_EDGES + e];
        else        d = ((const int*)ei)[N_EDGES + e];
        atomicAdd(&g_deg[d], 1);
    }
}

// ---- tile sum + (last block) scan of tile sums ----
__global__ __launch_bounds__(SCAN_TILE)
void tile_sum_scan_kernel() {
    __shared__ int wsum[32];
    __shared__ int is_last;
    int tid = threadIdx.x, lane = tid & 31, wid = tid >> 5;
    int i = blockIdx.x * SCAN_TILE + tid;
    int d = (i < N_NODES) ? g_deg[i] : 0;
    int v = d;
    #pragma unroll
    for (int off = 16; off > 0; off >>= 1)
        v += __shfl_down_sync(0xffffffffu, v, off);
    if (lane == 0) wsum[wid] = v;
    __syncthreads();
    if (wid == 0) {
        int t2 = (lane < 32) ? wsum[lane] : 0;
        #pragma unroll
        for (int off = 16; off > 0; off >>= 1)
            t2 += __shfl_down_sync(0xffffffffu, t2, off);
        if (lane == 0) {
            g_tilesum[blockIdx.x] = t2;
            __threadfence();
            int t = atomicAdd(&g_ticket, 1);
            is_last = (t == N_TILES - 1);
        }
    }
    __syncthreads();
    if (is_last && wid == 0) {
        // single warp scans 49 tile sums
        int run = 0;
        for (int base = 0; base < N_TILES; base += 32) {
            int idx = base + lane;
            int val = (idx < N_TILES) ? g_tilesum[idx] : 0;
            int incl = val;
            #pragma unroll
            for (int off = 1; off < 32; off <<= 1) {
                int t2 = __shfl_up_sync(0xffffffffu, incl, off);
                if (lane >= off) incl += t2;
            }
            if (idx < N_TILES) g_tileoff[idx] = run + incl - val;
            int tot = __shfl_sync(0xffffffffu, incl, 31);
            run += tot;
        }
        if (lane == 0) g_tileoff[N_TILES] = run;
    }
}

__global__ __launch_bounds__(SCAN_TILE)
void tile_write_kernel() {
    __shared__ int wsum[32];
    int tid = threadIdx.x, lane = tid & 31, wid = tid >> 5;
    int i = blockIdx.x * SCAN_TILE + tid;
    int d = (i < N_NODES) ? g_deg[i] : 0;
    int incl = d;
    #pragma unroll
    for (int off = 1; off < 32; off <<= 1) {
        int v = __shfl_up_sync(0xffffffffu, incl, off);
        if (lane >= off) incl += v;
    }
    if (lane == 31) wsum[wid] = incl;
    __syncthreads();
    if (wid == 0) {
        int v = wsum[lane];
        int wi = v;
        #pragma unroll
        for (int off = 1; off < 32; off <<= 1) {
            int t2 = __shfl_up_sync(0xffffffffu, wi, off);
            if (lane >= off) wi += t2;
        }
        wsum[lane] = wi - v;
    }
    __syncthreads();
    int excl = g_tileoff[blockIdx.x] + wsum[wid] + incl - d;
    if (i < N_NODES) {
        g_rowptr[i] = excl;
        g_cursor[i] = excl;
        g_dinv[i]   = rsqrtf((float)d + 1.0f);
    }
    if (i == N_NODES - 1) g_rowptr[N_NODES] = g_tileoff[N_TILES];
}

__global__ void build_csr_kernel(const void* ei) {
    for (int e = blockIdx.x * blockDim.x + threadIdx.x; e < N_EDGES;
         e += gridDim.x * blockDim.x) {
        int s, d;
        load_edge(ei, e, s, d);
        int pos = atomicAdd(&g_cursor[d], 1);
        float w = g_dinv[s];
        unsigned long long rec =
            ((unsigned long long)__float_as_uint(w) << 32) | (unsigned)s;
        g_csr[pos] = rec;
    }
}

// ---------------- fp16 tensor-core GEMM (m16n8k16, fp32 acc, sw pipeline) -----
#define SA 20
#define SB 136

__global__ __launch_bounds__(256)
void gemm_fp16_kernel(const float* __restrict__ A_in, const float* __restrict__ W,
                      const float* __restrict__ bias, float* __restrict__ C,
                      __half* __restrict__ C_half,
                      int N, int K, int do_relu,
                      const float* __restrict__ t_in,
                      const float* __restrict__ st_sum, const float* __restrict__ st_sq,
                      const float* __restrict__ gma, const float* __restrict__ bta,
                      const float* __restrict__ hres, float* __restrict__ h_out,
                      int add_res) {
    __shared__ unsigned As[128 * SA];
    __shared__ unsigned Bs[16 * SB];
    __shared__ float s_sc[HID], s_sh[HID];

    int tid = threadIdx.x;
    int w = tid >> 5, lane = tid & 31;
    int wm = (w & 1) * 64;
    int wn = (w >> 1) * 32;
    int gid = lane >> 2, tig = lane & 3;
    int row0 = blockIdx.x * 128;

    if (t_in && tid < HID) {
        float mu  = st_sum[tid] * (1.0f / N_NODES);
        float var = st_sq[tid] * (1.0f / N_NODES) - mu * mu;
        float sc  = gma[tid] * rsqrtf(var + BN_EPS);
        s_sc[tid] = sc;
        s_sh[tid] = bta[tid] - mu * sc;
    }
    __syncthreads();

    // per-thread staging coordinates
    int a_r  = tid >> 3;          // 0..31 (+p*32)
    int a_kk = (tid & 7) * 4;
    int b_k2 = tid >> 5;          // 0..7 (+p*8)
    int b_c  = (tid & 31) * 4;

    float4 a_reg[4];
    float4 blo_reg[2], bhi_reg[2];

    // load global tile (k0) into registers; fused BN+relu+res for A when t_in
    auto load_global = [&](int k0) {
        #pragma unroll
        for (int p = 0; p < 4; p++) {
            int r = p * 32 + a_r;
            int grow = row0 + r;
            float4 v = make_float4(0.f, 0.f, 0.f, 0.f);
            if (grow < N) {
                size_t off = (size_t)grow * K + k0 + a_kk;
                if (t_in) {
                    int c = k0 + a_kk;
                    float4 tv = *(const float4*)&t_in[off];
                    v.x = fmaxf(tv.x * s_sc[c + 0] + s_sh[c + 0], 0.f);
                    v.y = fmaxf(tv.y * s_sc[c + 1] + s_sh[c + 1], 0.f);
                    v.z = fmaxf(tv.z * s_sc[c + 2] + s_sh[c + 2], 0.f);
                    v.w = fmaxf(tv.w * s_sc[c + 3] + s_sh[c + 3], 0.f);
                    if (add_res) {
                        float4 rv = *(const float4*)&hres[off];
                        v.x += rv.x; v.y += rv.y; v.z += rv.z; v.w += rv.w;
                    }
                    *(float4*)&h_out[off] = v;
                } else {
                    v = *(const float4*)&A_in[off];
                }
            }
            a_reg[p] = v;
        }
        #pragma unroll
        for (int p = 0; p < 2; p++) {
            int k2 = p * 8 + b_k2;
            blo_reg[p] = *(const float4*)&W[(size_t)(k0 + 2 * k2)     * HID + b_c];
            bhi_reg[p] = *(const float4*)&W[(size_t)(k0 + 2 * k2 + 1) * HID + b_c];
        }
    };

    auto store_smem = [&]() {
        #pragma unroll
        for (int p = 0; p < 4; p++) {
            int r = p * 32 + a_r;
            float4 v = a_reg[p];
            __half2 h0 = __floats2half2_rn(v.x, v.y);
            __half2 h1 = __floats2half2_rn(v.z, v.w);
            uint2 u = make_uint2(*(unsigned*)&h0, *(unsigned*)&h1);
            *(uint2*)&As[r * SA + (a_kk >> 1)] = u;
        }
        #pragma unroll
        for (int p = 0; p < 2; p++) {
            int k2 = p * 8 + b_k2;
            float4 lo = blo_reg[p], hi = bhi_reg[p];
            __half2 q0 = __floats2half2_rn(lo.x, hi.x);
            __half2 q1 = __floats2half2_rn(lo.y, hi.y);
            __half2 q2 = __floats2half2_rn(lo.z, hi.z);
            __half2 q3 = __floats2half2_rn(lo.w, hi.w);
            uint4 u = make_uint4(*(unsigned*)&q0, *(unsigned*)&q1,
                                 *(unsigned*)&q2, *(unsigned*)&q3);
            *(uint4*)&Bs[k2 * SB + b_c] = u;
        }
    };

    float acc[4][4][4];
    #pragma unroll
    for (int i = 0; i < 4; i++)
        #pragma unroll
        for (int j = 0; j < 4; j++)
            #pragma unroll
            for (int c = 0; c < 4; c++) acc[i][j][c] = 0.f;

    load_global(0);
    for (int k0 = 0; k0 < K; k0 += 32) {
        store_smem();
        __syncthreads();
        if (k0 + 32 < K) load_global(k0 + 32);

        #pragma unroll
        for (int s = 0; s < 2; s++) {
            int base = s * 8;
            unsigned afr[4][4], bfr[4][2];
            #pragma unroll
            for (int i = 0; i < 4; i++) {
                int m = wm + i * 16;
                afr[i][0] = As[(m + gid)     * SA + base + tig];
                afr[i][1] = As[(m + gid + 8) * SA + base + tig];
                afr[i][2] = As[(m + gid)     * SA + base + tig + 4];
                afr[i][3] = As[(m + gid + 8) * SA + base + tig + 4];
            }
            #pragma unroll
            for (int j = 0; j < 4; j++) {
                int n = wn + j * 8 + gid;
                bfr[j][0] = Bs[(base + tig)     * SB + n];
                bfr[j][1] = Bs[(base + tig + 4) * SB + n];
            }
            #pragma unroll
            for (int i = 0; i < 4; i++)
                #pragma unroll
                for (int j = 0; j < 4; j++) {
                    asm volatile(
                        "mma.sync.aligned.m16n8k16.row.col.f32.f16.f16.f32 "
                        "{%0,%1,%2,%3}, {%4,%5,%6,%7}, {%8,%9}, {%0,%1,%2,%3};"
                        : "+f"(acc[i][j][0]), "+f"(acc[i][j][1]),
                          "+f"(acc[i][j][2]), "+f"(acc[i][j][3])
                        : "r"(afr[i][0]), "r"(afr[i][1]),
                          "r"(afr[i][2]), "r"(afr[i][3]),
                          "r"(bfr[j][0]), "r"(bfr[j][1]));
                }
        }
        __syncthreads();
    }

    #pragma unroll
    for (int i = 0; i < 4; i++) {
        int r_up = row0 + wm + i * 16 + gid;
        int r_dn = r_up + 8;
        #pragma unroll
        for (int j = 0; j < 4; j++) {
            int col = wn + j * 8 + 2 * tig;
            float b0 = bias ? bias[col]     : 0.f;
            float b1 = bias ? bias[col + 1] : 0.f;
            float u0 = acc[i][j][0] + b0, u1 = acc[i][j][1] + b1;
            float d0 = acc[i][j][2] + b0, d1 = acc[i][j][3] + b1;
            if (do_relu) {
                u0 = fmaxf(u0, 0.f); u1 = fmaxf(u1, 0.f);
                d0 = fmaxf(d0, 0.f); d1 = fmaxf(d1, 0.f);
            }
            if (C_half) {
                if (r_up < N)
                    *(__half2*)&C_half[(size_t)r_up * HID + col] = __floats2half2_rn(u0, u1);
                if (r_dn < N)
                    *(__half2*)&C_half[(size_t)r_dn * HID + col] = __floats2half2_rn(d0, d1);
            } else {
                if (r_up < N) *(float2*)&C[(size_t)r_up * HID + col] = make_float2(u0, u1);
                if (r_dn < N) *(float2*)&C[(size_t)r_dn * HID + col] = make_float2(d0, d1);
            }
        }
    }
}

// ---------------- aggregation (fp16 gather, packed CSR) -----------------------
__global__ __launch_bounds__(256)
void agg_kernel(const __half* __restrict__ hw, const float* __restrict__ bc,
                float* __restrict__ t, float* __restrict__ st_sum,
                float* __restrict__ st_sq) {
    __shared__ float s_sum[HID], s_sq[HID];
    int tid = threadIdx.x;
    if (tid < HID) { s_sum[tid] = 0.f; s_sq[tid] = 0.f; }
    __syncthreads();

    int lane = tid & 31;
    int n = blockIdx.x * 8 + (tid >> 5);
    if (n < N_NODES) {
        int e0 = g_rowptr[n], e1 = g_rowptr[n + 1];
        float a0 = 0.f, a1 = 0.f, a2 = 0.f, a3 = 0.f;
        int e = e0;
        unsigned long long r0 = 0, r1 = 0;
        if (e < e1)     r0 = __ldg(&g_csr[e]);
        if (e + 1 < e1) r1 = __ldg(&g_csr[e + 1]);
        while (e < e1) {
            unsigned long long rec = r0;
            r0 = r1;
            if (e + 2 < e1) r1 = __ldg(&g_csr[e + 2]);
            int s   = (int)(unsigned)rec;
            float w = __uint_as_float((unsigned)(rec >> 32));
            uint2 u = __ldg((const uint2*)(hw + (size_t)s * HID) + lane);
            float2 f0 = __half22float2(*(const __half2*)&u.x);
            float2 f1 = __half22float2(*(const __half2*)&u.y);
            a0 += f0.x * w; a1 += f0.y * w; a2 += f1.x * w; a3 += f1.y * w;
            e++;
        }
        float di  = g_dinv[n];
        float dii = di * di;
        int c = lane * 4;
        uint2 su = __ldg((const uint2*)(hw + (size_t)n * HID) + lane);
        float2 sf0 = __half22float2(*(const __half2*)&su.x);
        float2 sf1 = __half22float2(*(const __half2*)&su.y);
        float t0 = a0 * di + sf0.x * dii + bc[c + 0];
        float t1 = a1 * di + sf0.y * dii + bc[c + 1];
        float t2 = a2 * di + sf1.x * dii + bc[c + 2];
        float t3 = a3 * di + sf1.y * dii + bc[c + 3];
        *(float4*)(t + (size_t)n * HID + c) = make_float4(t0, t1, t2, t3);
        atomicAdd(&s_sum[c + 0], t0); atomicAdd(&s_sq[c + 0], t0 * t0);
        atomicAdd(&s_sum[c + 1], t1); atomicAdd(&s_sq[c + 1], t1 * t1);
        atomicAdd(&s_sum[c + 2], t2); atomicAdd(&s_sq[c + 2], t2 * t2);
        atomicAdd(&s_sum[c + 3], t3); atomicAdd(&s_sq[c + 3], t3 * t3);
    }
    __syncthreads();
    if (tid < HID) {
        atomicAdd(&st_sum[tid], s_sum[tid]);
        atomicAdd(&st_sq[tid],  s_sq[tid]);
    }
}

// ------- output projection fused with final BN+relu+residual ------------------
__global__ __launch_bounds__(256)
void out_kernel(const float* __restrict__ t, const float* __restrict__ hres,
                const float* __restrict__ st_sum, const float* __restrict__ st_sq,
                const float* __restrict__ gma, const float* __restrict__ bta,
                const float* __restrict__ Wo, const float* __restrict__ bo,
                float* __restrict__ out) {
    __shared__ float ws[HID * OUT_DIM];
    __shared__ float bs[OUT_DIM];
    __shared__ float s_sc[HID], s_sh[HID];
    int tid = threadIdx.x;
    for (int i = tid; i < HID * OUT_DIM; i += blockDim.x) ws[i] = Wo[i];
    if (tid < OUT_DIM) bs[tid] = bo[tid];
    if (tid < HID) {
        float mu  = st_sum[tid] * (1.0f / N_NODES);
        float var = st_sq[tid] * (1.0f / N_NODES) - mu * mu;
        float sc  = gma[tid] * rsqrtf(var + BN_EPS);
        s_sc[tid] = sc;
        s_sh[tid] = bta[tid] - mu * sc;
    }
    __syncthreads();
    int n = blockIdx.x * blockDim.x + tid;
    if (n >= N_NODES) return;
    float acc[OUT_DIM];
    #pragma unroll
    for (int o = 0; o < OUT_DIM; o++) acc[o] = bs[o];
    const float4* tp = (const float4*)(t + (size_t)n * HID);
    const float4* rp = (const float4*)(hres + (size_t)n * HID);
    #pragma unroll 4
    for (int k4 = 0; k4 < HID / 4; k4++) {
        float4 tv = tp[k4];
        float4 rv = rp[k4];
        int kb = k4 * 4;
        float a0 = fmaxf(tv.x * s_sc[kb + 0] + s_sh[kb + 0], 0.f) + rv.x;
        float a1 = fmaxf(tv.y * s_sc[kb + 1] + s_sh[kb + 1], 0.f) + rv.y;
        float a2 = fmaxf(tv.z * s_sc[kb + 2] + s_sh[kb + 2], 0.f) + rv.z;
        float a3 = fmaxf(tv.w * s_sc[kb + 3] + s_sh[kb + 3], 0.f) + rv.w;
        #pragma unroll
        for (int o = 0; o < OUT_DIM; o++) {
            acc[o] += a0 * ws[(kb + 0) * OUT_DIM + o]
                    + a1 * ws[(kb + 1) * OUT_DIM + o]
                    + a2 * ws[(kb + 2) * OUT_DIM + o]
                    + a3 * ws[(kb + 3) * OUT_DIM + o];
        }
    }
    #pragma unroll
    for (int o = 0; o < OUT_DIM; o++) out[n * OUT_DIM + o] = acc[o];
}

// ---------------- launch ----------------
extern "C" void kernel_launch(void* const* d_in, const int* in_sizes, int n_in,
                              void* d_out, int out_size) {
    const float* x     = (const float*)d_in[0];
    const void*  ei    = d_in[1];
    const float* W_in  = (const float*)d_in[2];
    const float* b_in  = (const float*)d_in[3];
    const float* Wc    = (const float*)d_in[4];
    const float* bc    = (const float*)d_in[5];
    const float* gamma = (const float*)d_in[6];
    const float* beta  = (const float*)d_in[7];
    const float* W_out = (const float*)d_in[8];
    const float* b_out = (const float*)d_in[9];
    float* out = (float*)d_out;

    float *p_h, *p_t, *p_sum, *p_sq;
    __half* p_hwh;
    cudaGetSymbolAddress((void**)&p_h,   g_h);
    cudaGetSymbolAddress((void**)&p_hwh, g_hwh);
    cudaGetSymbolAddress((void**)&p_t,   g_t);
    cudaGetSymbolAddress((void**)&p_sum, g_sum);
    cudaGetSymbolAddress((void**)&p_sq,  g_sumsq);

    static cudaStream_t s_side = nullptr;
    static cudaEvent_t ev_fork = nullptr, ev_join = nullptr;
    if (!s_side) {
        cudaStreamCreateWithFlags(&s_side, cudaStreamNonBlocking);
        cudaEventCreateWithFlags(&ev_fork, cudaEventDisableTiming);
        cudaEventCreateWithFlags(&ev_join, cudaEventDisableTiming);
    }

    // fork: CSR build on side stream, overlapped with input + layer-0 GEMMs
    cudaEventRecord(ev_fork, 0);
    cudaStreamWaitEvent(s_side, ev_fork, 0);
    detect_zero_kernel<<<99, 512, 0, s_side>>>(ei);
    count_deg_kernel<<<586, 1024, 0, s_side>>>(ei);
    tile_sum_scan_kernel<<<N_TILES, SCAN_TILE, 0, s_side>>>();
    tile_write_kernel<<<N_TILES, SCAN_TILE, 0, s_side>>>();
    build_csr_kernel<<<586, 1024, 0, s_side>>>(ei);
    cudaEventRecord(ev_join, s_side);

    int grid = (N_NODES + 127) / 128;
    // input layer: h = relu(x @ W_in + b_in), fp32 out
    gemm_fp16_kernel<<<grid, 256>>>(x, W_in, b_in, p_h, nullptr,
                                    N_NODES, IN_DIM, 1,
                                    nullptr, nullptr, nullptr, nullptr, nullptr,
                                    nullptr, nullptr, 0);
    // layer 0 conv gemm: hw (fp16) = h @ Wc0
    gemm_fp16_kernel<<<grid, 256>>>(p_h, Wc, nullptr, nullptr, p_hwh,
                                    N_NODES, HID, 0,
                                    nullptr, nullptr, nullptr, nullptr, nullptr,
                                    nullptr, nullptr, 0);
    // join: agg needs CSR
    cudaStreamWaitEvent(0, ev_join, 0);
    agg_kernel<<<N_NODES / 8, 256>>>(p_hwh, bc, p_t, p_sum, p_sq);

    // layer 1: gemm fused with BN(stats0)+relu, writes h1 (fp32) and hw (fp16)
    gemm_fp16_kernel<<<grid, 256>>>(nullptr, Wc + 1 * HID * HID, nullptr,
                                    nullptr, p_hwh,
                                    N_NODES, HID, 0,
                                    p_t, p_sum, p_sq, gamma, beta,
                                    nullptr, p_h, 0);
    agg_kernel<<<N_NODES / 8, 256>>>(p_hwh, bc + HID, p_t, p_sum + HID, p_sq + HID);

    // layer 2: gemm fused with BN(stats1)+relu+residual(h1), writes h2, hw fp16
    gemm_fp16_kernel<<<grid, 256>>>(nullptr, Wc + 2 * HID * HID, nullptr,
                                    nullptr, p_hwh,
                                    N_NODES, HID, 0,
                                    p_t, p_sum + HID, p_sq + HID,
                                    gamma + HID, beta + HID,
                                    p_h, p_h, 1);
    agg_kernel<<<N_NODES / 8, 256>>>(p_hwh, bc + 2 * HID, p_t,
                                     p_sum + 2 * HID, p_sq + 2 * HID);

    // output: fused BN(stats2)+relu+residual(h2) then @ W_out + b_out
    out_kernel<<<(N_NODES + 255) / 256, 256>>>(p_t, p_h,
                                               p_sum + 2 * HID, p_sq + 2 * HID,
                                               gamma + 2 * HID, beta + 2 * HID,
                                               W_out, b_out, out);
}